// round 7
// baseline (speedup 1.0000x reference)
#include <cuda_runtime.h>
#include <cstdint>

#define B_ 16
#define C_ 128
#define T_ 16384
#define H_ 4
#define D_ 32
#define CT (C_ * T_)

__device__ float g_eq[B_ * CT];
__device__ float g_ek[B_ * CT];
__device__ float g_v [B_ * CT];
__device__ float g_op[B_ * CT];
__device__ float g_Sq[B_ * C_];
__device__ float g_Sk[B_ * C_];
__device__ float g_ctx[B_ * H_ * D_ * D_];
__device__ float g_stats[B_ * 2];

__device__ __forceinline__ float tf32r(float x) {
    uint32_t y;
    asm("cvt.rna.tf32.f32 %0, %1;" : "=r"(y) : "f"(x));
    return __uint_as_float(y);
}
__device__ __forceinline__ void mma_tf32(float* d, const uint32_t* a, const uint32_t* b2) {
    asm volatile("mma.sync.aligned.m16n8k8.row.col.f32.tf32.tf32.f32 "
        "{%0,%1,%2,%3}, {%4,%5,%6,%7}, {%8,%9}, {%0,%1,%2,%3};"
        : "+f"(d[0]), "+f"(d[1]), "+f"(d[2]), "+f"(d[3])
        : "r"(a[0]), "r"(a[1]), "r"(a[2]), "r"(a[3]), "r"(b2[0]), "r"(b2[1]));
}

// ============================ group bodies ===================================

// ---- qkv: 3-slab GEMM with resident x tile (R6-proven) ----------------------
__device__ __forceinline__ void qkv_body(int b, int t0, const float* __restrict__ x,
                                         const float* __restrict__ wqkv, float* dsm) {
    float (*Bs)[136] = (float(*)[136])dsm;              // x tile [128][136]
    float (*As)[36]  = (float(*)[36])(dsm + 128 * 136); // W chunk
    float* rsum      = dsm + 128 * 136 + 128 * 36;
    const int tid = threadIdx.x, lane = tid & 31, wid = tid >> 5;
    const int wm = (wid >> 1) * 32, wn = (wid & 1) * 64;

    const float* xb = x + (size_t)b * CT;
#pragma unroll
    for (int it = 0; it < 16; it++) {
        int idx = tid + it * 256, row = idx >> 5, c4 = (idx & 31) * 4;
        float4 v = *(const float4*)(xb + (size_t)row * T_ + t0 + c4);
        *(float4*)&Bs[row][c4] = make_float4(tf32r(v.x), tf32r(v.y),
                                             tf32r(v.z), tf32r(v.w));
    }

    for (int ot = 0; ot < 3; ot++) {
        float acc[2][8][4];
#pragma unroll
        for (int mi = 0; mi < 2; mi++)
#pragma unroll
            for (int ni = 0; ni < 8; ni++)
#pragma unroll
                for (int r = 0; r < 4; r++) acc[mi][ni][r] = 0.f;

        for (int kc = 0; kc < 4; kc++) {
            __syncthreads();
#pragma unroll
            for (int it = 0; it < 4; it++) {
                int idx = tid + it * 256, row = idx >> 3, c4 = (idx & 7) * 4;
                float4 v = *(const float4*)(wqkv + (size_t)(ot * 128 + row) * 128
                                            + kc * 32 + c4);
                *(float4*)&As[row][c4] = make_float4(tf32r(v.x), tf32r(v.y),
                                                     tf32r(v.z), tf32r(v.w));
            }
            __syncthreads();
#pragma unroll
            for (int k8 = 0; k8 < 4; k8++) {
                const int k = k8 * 8;
                uint32_t af[2][4], bf[8][2];
#pragma unroll
                for (int mi = 0; mi < 2; mi++) {
                    int r = wm + mi * 16 + (lane >> 2);
                    af[mi][0] = __float_as_uint(As[r    ][k +     (lane & 3)]);
                    af[mi][1] = __float_as_uint(As[r + 8][k +     (lane & 3)]);
                    af[mi][2] = __float_as_uint(As[r    ][k + 4 + (lane & 3)]);
                    af[mi][3] = __float_as_uint(As[r + 8][k + 4 + (lane & 3)]);
                }
#pragma unroll
                for (int ni = 0; ni < 8; ni++) {
                    int n = wn + ni * 8 + (lane >> 2);
                    bf[ni][0] = __float_as_uint(Bs[kc * 32 + k +     (lane & 3)][n]);
                    bf[ni][1] = __float_as_uint(Bs[kc * 32 + k + 4 + (lane & 3)][n]);
                }
#pragma unroll
                for (int mi = 0; mi < 2; mi++)
#pragma unroll
                    for (int ni = 0; ni < 8; ni++)
                        mma_tf32(acc[mi][ni], af[mi], bf[ni]);
            }
        }

        float* dst = (ot == 0 ? g_eq : (ot == 1 ? g_ek : g_v)) + (size_t)b * CT;
        if (ot == 2) {
#pragma unroll
            for (int mi = 0; mi < 2; mi++)
#pragma unroll
                for (int half = 0; half < 2; half++) {
                    int r = wm + mi * 16 + (lane >> 2) + half * 8;
#pragma unroll
                    for (int ni = 0; ni < 8; ni++)
                        *(float2*)(dst + (size_t)r * T_ + t0 + wn + ni * 8
                                   + 2 * (lane & 3)) =
                            make_float2(acc[mi][ni][half * 2],
                                        acc[mi][ni][half * 2 + 1]);
                }
        } else {
            __syncthreads();
            if (tid < 128) rsum[tid] = 0.f;
            __syncthreads();
#pragma unroll
            for (int mi = 0; mi < 2; mi++)
#pragma unroll
                for (int half = 0; half < 2; half++) {
                    int r = wm + mi * 16 + (lane >> 2) + half * 8;
                    float s = 0.f;
#pragma unroll
                    for (int ni = 0; ni < 8; ni++) {
                        float e0 = __expf(acc[mi][ni][half * 2]);
                        float e1 = __expf(acc[mi][ni][half * 2 + 1]);
                        s += e0 + e1;
                        *(float2*)(dst + (size_t)r * T_ + t0 + wn + ni * 8
                                   + 2 * (lane & 3)) = make_float2(e0, e1);
                    }
                    s += __shfl_xor_sync(0xffffffffu, s, 1);
                    s += __shfl_xor_sync(0xffffffffu, s, 2);
                    if ((lane & 3) == 0) atomicAdd(&rsum[r], s);
                }
            __syncthreads();
            float* S = (ot == 0 ? g_Sq : g_Sk) + b * C_;
            if (tid < 128) atomicAdd(&S[tid], rsum[tid]);
        }
    }
}

// ---- ctx: tensor-core k.v^T contraction (R6-proven) --------------------------
__device__ __forceinline__ void ctx_body(int b, int sp, int h, float* dsm) {
    float (*ks)[68] = (float(*)[68])dsm;
    float (*vs)[68] = (float(*)[68])(dsm + 32 * 68);
    float* cacc     = dsm + 2 * 32 * 68;
    const float* K = g_ek + (size_t)(b * C_ + h * D_) * T_;
    const float* V = g_v  + (size_t)(b * C_ + h * D_) * T_;
    const int tid = threadIdx.x, lane = tid & 31, wid = tid >> 5;
    const int kb = wid * 8;

    for (int i = tid; i < D_ * D_; i += 256) cacc[i] = 0.f;

    float acc[2][4][4];
#pragma unroll
    for (int mi = 0; mi < 2; mi++)
#pragma unroll
        for (int ni = 0; ni < 4; ni++)
#pragma unroll
            for (int r = 0; r < 4; r++) acc[mi][ni][r] = 0.f;

    const int l2 = tid * 2;
    for (int n0 = sp * 512; n0 < sp * 512 + 512; n0 += 64) {
#pragma unroll
        for (int q = 0; q < 2; q++) {
            int li = l2 + q, r = li >> 4, c4 = (li & 15) * 4;
            float4 kv = *(const float4*)(K + (size_t)r * T_ + n0 + c4);
            float4 vv = *(const float4*)(V + (size_t)r * T_ + n0 + c4);
            *(float4*)&ks[r][c4] = make_float4(tf32r(kv.x), tf32r(kv.y),
                                               tf32r(kv.z), tf32r(kv.w));
            *(float4*)&vs[r][c4] = make_float4(tf32r(vv.x), tf32r(vv.y),
                                               tf32r(vv.z), tf32r(vv.w));
        }
        __syncthreads();
        uint32_t af[2][4], bf[4][2];
#pragma unroll
        for (int mi = 0; mi < 2; mi++) {
            int r = mi * 16 + (lane >> 2);
            af[mi][0] = __float_as_uint(ks[r    ][kb +     (lane & 3)]);
            af[mi][1] = __float_as_uint(ks[r + 8][kb +     (lane & 3)]);
            af[mi][2] = __float_as_uint(ks[r    ][kb + 4 + (lane & 3)]);
            af[mi][3] = __float_as_uint(ks[r + 8][kb + 4 + (lane & 3)]);
        }
#pragma unroll
        for (int ni = 0; ni < 4; ni++) {
            int n = ni * 8 + (lane >> 2);
            bf[ni][0] = __float_as_uint(vs[n][kb +     (lane & 3)]);
            bf[ni][1] = __float_as_uint(vs[n][kb + 4 + (lane & 3)]);
        }
#pragma unroll
        for (int mi = 0; mi < 2; mi++)
#pragma unroll
            for (int ni = 0; ni < 4; ni++)
                mma_tf32(acc[mi][ni], af[mi], bf[ni]);
        __syncthreads();
    }
#pragma unroll
    for (int mi = 0; mi < 2; mi++)
#pragma unroll
        for (int ni = 0; ni < 4; ni++)
#pragma unroll
            for (int r = 0; r < 4; r++) {
                int d = mi * 16 + (lane >> 2) + (r >> 1) * 8;
                int e = ni * 8 + (lane & 3) * 2 + (r & 1);
                atomicAdd(&cacc[d * D_ + e], acc[mi][ni][r]);
            }
    __syncthreads();
    float* Cp = g_ctx + (size_t)(b * H_ + h) * (D_ * D_);
    for (int i = tid; i < D_ * D_; i += 256) atomicAdd(&Cp[i], cacc[i]);
}

// ---- out: M built in SMEM (k_M folded), then GEMM + bias + GN moments -------
__device__ __forceinline__ void out_body(int b, int t0,
                                         const float* __restrict__ w_out,
                                         const float* __restrict__ b_out,
                                         float* dsm) {
    float (*Ms)[132] = (float(*)[132])dsm;                 // M tile, pad 132
    float (*Bs)[136] = (float(*)[136])(dsm + 128 * 132);   // eq chunk
    float* cf        = (float*)Bs;                          // reuse pre-GEMM
    const int tid = threadIdx.x, lane = tid & 31, wid = tid >> 5;
    const int wm = (wid >> 1) * 32, wn = (wid & 1) * 64;
    const float scale = 0.17677669529663687f;  // 32^-0.5

    // M prologue: cf = scale*ctx/(Sk*Sq), then M = w_out x cf (tf32-rounded)
    for (int i = tid; i < H_ * D_ * D_; i += 256) {
        int h = i >> 10, d = (i >> 5) & 31;
        float sk = g_Sk[b * C_ + h * D_ + d], sq = g_Sq[b * C_ + h * D_ + d];
        cf[i] = scale * g_ctx[b * (H_ * D_ * D_) + i] / (sk * sq);
    }
    __syncthreads();
    for (int i = tid; i < C_ * C_; i += 256) {
        int o = i >> 7, hd = i & 127, h = hd >> 5, d = hd & 31;
        const float* wr = w_out + o * C_ + h * D_;
        const float* cr = cf + (h * D_ + d) * D_;
        float s0 = 0, s1 = 0, s2 = 0, s3 = 0;
#pragma unroll
        for (int e = 0; e < 32; e += 4) {
            s0 = fmaf(wr[e    ], cr[e    ], s0);
            s1 = fmaf(wr[e + 1], cr[e + 1], s1);
            s2 = fmaf(wr[e + 2], cr[e + 2], s2);
            s3 = fmaf(wr[e + 3], cr[e + 3], s3);
        }
        Ms[o][hd] = tf32r((s0 + s1) + (s2 + s3));
    }

    // GEMM: out = M @ eq, B chunks prefetched from global
    const float* Bg = g_eq + (size_t)b * CT;
    float acc[2][8][4];
#pragma unroll
    for (int mi = 0; mi < 2; mi++)
#pragma unroll
        for (int ni = 0; ni < 8; ni++)
#pragma unroll
            for (int r = 0; r < 4; r++) acc[mi][ni][r] = 0.f;

    float4 bpre[4];
#pragma unroll
    for (int it = 0; it < 4; it++) {
        int idx = tid + it * 256, row = idx >> 5, c4 = idx & 31;
        bpre[it] = *(const float4*)(Bg + (size_t)row * T_ + t0 + c4 * 4);
    }
    for (int kc = 0; kc < 4; kc++) {
        __syncthreads();
#pragma unroll
        for (int it = 0; it < 4; it++) {
            int idx = tid + it * 256, row = idx >> 5, c4 = idx & 31;
            float4 v = bpre[it];
            *(float4*)&Bs[row][c4 * 4] = make_float4(tf32r(v.x), tf32r(v.y),
                                                     tf32r(v.z), tf32r(v.w));
        }
        __syncthreads();
        if (kc < 3) {
#pragma unroll
            for (int it = 0; it < 4; it++) {
                int idx = tid + it * 256, row = idx >> 5, c4 = idx & 31;
                bpre[it] = *(const float4*)(Bg + (size_t)((kc + 1) * 32 + row) * T_
                                            + t0 + c4 * 4);
            }
        }
#pragma unroll
        for (int k8 = 0; k8 < 4; k8++) {
            const int k = kc * 32 + k8 * 8, ks = k8 * 8;
            uint32_t af[2][4], bf[8][2];
#pragma unroll
            for (int mi = 0; mi < 2; mi++) {
                int r = wm + mi * 16 + (lane >> 2);
                af[mi][0] = __float_as_uint(Ms[r    ][k +     (lane & 3)]);
                af[mi][1] = __float_as_uint(Ms[r + 8][k +     (lane & 3)]);
                af[mi][2] = __float_as_uint(Ms[r    ][k + 4 + (lane & 3)]);
                af[mi][3] = __float_as_uint(Ms[r + 8][k + 4 + (lane & 3)]);
            }
#pragma unroll
            for (int ni = 0; ni < 8; ni++) {
                int n = wn + ni * 8 + (lane >> 2);
                bf[ni][0] = __float_as_uint(Bs[ks +     (lane & 3)][n]);
                bf[ni][1] = __float_as_uint(Bs[ks + 4 + (lane & 3)][n]);
            }
#pragma unroll
            for (int mi = 0; mi < 2; mi++)
#pragma unroll
                for (int ni = 0; ni < 8; ni++)
                    mma_tf32(acc[mi][ni], af[mi], bf[ni]);
        }
    }

    float* dst = g_op + (size_t)b * CT;
    float s1 = 0.f, s2 = 0.f;
#pragma unroll
    for (int mi = 0; mi < 2; mi++)
#pragma unroll
        for (int half = 0; half < 2; half++) {
            int r = wm + mi * 16 + (lane >> 2) + half * 8;
            float bo = __ldg(&b_out[r]);
#pragma unroll
            for (int ni = 0; ni < 8; ni++) {
                float v0 = acc[mi][ni][half * 2]     + bo;
                float v1 = acc[mi][ni][half * 2 + 1] + bo;
                s1 += v0 + v1;
                s2 = fmaf(v0, v0, s2); s2 = fmaf(v1, v1, s2);
                *(float2*)(dst + (size_t)r * T_ + t0 + wn + ni * 8
                           + 2 * (lane & 3)) = make_float2(v0, v1);
            }
        }
#pragma unroll
    for (int o = 16; o > 0; o >>= 1) {
        s1 += __shfl_down_sync(0xffffffffu, s1, o);
        s2 += __shfl_down_sync(0xffffffffu, s2, o);
    }
    if (lane == 0) {
        atomicAdd(&g_stats[b * 2 + 0], s1);
        atomicAdd(&g_stats[b * 2 + 1], s2);
    }
}

// ---- norm: one (b, c) row per block, 16 independent float4s -----------------
__device__ __forceinline__ void norm_body(int b, int c,
                                          const float* __restrict__ gnw,
                                          const float* __restrict__ gnb,
                                          float* __restrict__ out) {
    const int tid = threadIdx.x;
    const float inv = 1.0f / (float)CT;
    float m    = g_stats[b * 2 + 0] * inv;
    float var  = g_stats[b * 2 + 1] * inv - m * m;
    float rstd = rsqrtf(var + 1e-5f);
    float w    = gnw[c] * rstd;
    float bias = gnb[c] - m * w;
    const float* src = g_op + (size_t)b * CT + (size_t)c * T_;
    float*       dst = out  + (size_t)b * CT + (size_t)c * T_;
#pragma unroll
    for (int k = 0; k < 16; k++) {
        int idx = (k * 256 + tid) * 4;
        float4 v = *(const float4*)(src + idx);
        v.x = v.x * w + bias; v.y = v.y * w + bias;
        v.z = v.z * w + bias; v.w = v.w * w + bias;
        *(float4*)(dst + idx) = v;
    }
}

// ============================ kernels ========================================

__global__ void k_zero() {
    int i = blockIdx.x * 256 + threadIdx.x;
    if (i < B_ * C_)           { g_Sq[i] = 0.f; g_Sk[i] = 0.f; }
    if (i < B_ * H_ * D_ * D_) g_ctx[i] = 0.f;
    if (i < B_ * 2)            g_stats[i] = 0.f;
}

// Pipelined stage: groups interleaved mod 4 so each SM wave mixes mma + memory.
// j: qkv batches {2j,2j+1} (j<8); ctx {2j-2,2j-1} (1<=j<=8);
//    out {2j-4,2j-3} (2<=j<=9);  norm {2j-6,2j-5} (3<=j<=10).
__global__ __launch_bounds__(256, 2) void k_stage(int j,
        const float* __restrict__ x, const float* __restrict__ wqkv,
        const float* __restrict__ wout, const float* __restrict__ bout,
        const float* __restrict__ gnw, const float* __restrict__ gnb,
        float* __restrict__ out) {
    extern __shared__ float dsm[];
    const int grp = blockIdx.x & 3;
    const int sub = blockIdx.x >> 2;          // 0..255
    if (grp == 0) {
        if (j >= 8) return;
        qkv_body(2 * j + (sub >> 7), (sub & 127) * 128, x, wqkv, dsm);
    } else if (grp == 1) {
        if (j < 1 || j > 8) return;
        int rem = sub & 127;
        ctx_body(2 * (j - 1) + (sub >> 7), rem >> 2, rem & 3, dsm);
    } else if (grp == 2) {
        if (j < 2 || j > 9) return;
        out_body(2 * (j - 2) + (sub >> 7), (sub & 127) * 128, wout, bout, dsm);
    } else {
        if (j < 3 || j > 10) return;
        norm_body(2 * (j - 3) + (sub >> 7), sub & 127, gnw, gnb, out);
    }
}

#define STAGE_SMEM ((128 * 136 + 128 * 36 + 128) * 4)

// ---------------- launch ------------------------------------------------------
extern "C" void kernel_launch(void* const* d_in, const int* in_sizes, int n_in,
                              void* d_out, int out_size)
{
    const float* x    = (const float*)d_in[0];
    const float* wqkv = (const float*)d_in[1];
    const float* wout = (const float*)d_in[2];
    const float* bout = (const float*)d_in[3];
    const float* gnw  = (const float*)d_in[4];
    const float* gnb  = (const float*)d_in[5];
    float* out = (float*)d_out;

    cudaFuncSetAttribute(k_stage, cudaFuncAttributeMaxDynamicSharedMemorySize,
                         STAGE_SMEM);

    k_zero<<<256, 256>>>();
    for (int j = 0; j <= 10; j++)
        k_stage<<<1024, 256, STAGE_SMEM>>>(j, x, wqkv, wout, bout, gnw, gnb, out);
}

// round 8
// speedup vs baseline: 1.4301x; 1.4301x over previous
#include <cuda_runtime.h>
#include <cstdint>

#define B_ 16
#define C_ 128
#define T_ 16384
#define H_ 4
#define D_ 32
#define CT (C_ * T_)

__device__ float g_eq[B_ * CT];
__device__ float g_ek[B_ * CT];
__device__ float g_v [B_ * CT];
__device__ float g_op[B_ * CT];
__device__ float g_Sq[B_ * C_];
__device__ float g_Sk[B_ * C_];
__device__ float g_ctx[B_ * H_ * D_ * D_];
__device__ float g_stats[B_ * 2];

__device__ __forceinline__ float tf32r(float x) {
    uint32_t y;
    asm("cvt.rna.tf32.f32 %0, %1;" : "=r"(y) : "f"(x));
    return __uint_as_float(y);
}
__device__ __forceinline__ void mma_tf32(float* d, const uint32_t* a, const uint32_t* b2) {
    asm volatile("mma.sync.aligned.m16n8k8.row.col.f32.tf32.tf32.f32 "
        "{%0,%1,%2,%3}, {%4,%5,%6,%7}, {%8,%9}, {%0,%1,%2,%3};"
        : "+f"(d[0]), "+f"(d[1]), "+f"(d[2]), "+f"(d[3])
        : "r"(a[0]), "r"(a[1]), "r"(a[2]), "r"(a[3]), "r"(b2[0]), "r"(b2[1]));
}

// ---------------- K0: zero ---------------------------------------------------
__global__ void k_zero() {
    int i = blockIdx.x * 256 + threadIdx.x;
    if (i < B_ * C_)           { g_Sq[i] = 0.f; g_Sk[i] = 0.f; }
    if (i < B_ * H_ * D_ * D_) g_ctx[i] = 0.f;
    if (i < B_ * 2)            g_stats[i] = 0.f;
}

// ---------------- K1: QKV GEMM + exp + fused ctx -----------------------------
// SMEM map: Bs x-tile [128][136] | As W-chunk [128][36] | rsum[128] | cacc[1024]
#define QKV_SMEM ((128 * 136 + 128 * 36 + 128 + 1024) * 4)

__global__ __launch_bounds__(256, 2) void k_qkv(const float* __restrict__ x,
                                                const float* __restrict__ wqkv) {
    extern __shared__ float dsm[];
    float (*Bs)[136] = (float(*)[136])dsm;
    float (*As)[36]  = (float(*)[36])(dsm + 128 * 136);
    float* rsum      = dsm + 128 * 136 + 128 * 36;
    float* cacc      = rsum + 128;
    const int b = blockIdx.y, t0 = blockIdx.x * 128;
    const int tid = threadIdx.x, lane = tid & 31, wid = tid >> 5;
    const int wm = (wid >> 1) * 32, wn = (wid & 1) * 64;

    const float* xb = x + (size_t)b * CT;
#pragma unroll
    for (int it = 0; it < 16; it++) {                    // resident x tile
        int idx = tid + it * 256, row = idx >> 5, c4 = (idx & 31) * 4;
        float4 v = *(const float4*)(xb + (size_t)row * T_ + t0 + c4);
        *(float4*)&Bs[row][c4] = make_float4(tf32r(v.x), tf32r(v.y),
                                             tf32r(v.z), tf32r(v.w));
    }

    for (int ot = 0; ot < 3; ot++) {                     // q, k, v slabs
        float acc[2][8][4];
#pragma unroll
        for (int mi = 0; mi < 2; mi++)
#pragma unroll
            for (int ni = 0; ni < 8; ni++)
#pragma unroll
                for (int r = 0; r < 4; r++) acc[mi][ni][r] = 0.f;

        for (int kc = 0; kc < 4; kc++) {
            __syncthreads();
#pragma unroll
            for (int it = 0; it < 4; it++) {
                int idx = tid + it * 256, row = idx >> 3, c4 = (idx & 7) * 4;
                float4 v = *(const float4*)(wqkv + (size_t)(ot * 128 + row) * 128
                                            + kc * 32 + c4);
                *(float4*)&As[row][c4] = make_float4(tf32r(v.x), tf32r(v.y),
                                                     tf32r(v.z), tf32r(v.w));
            }
            __syncthreads();
#pragma unroll
            for (int k8 = 0; k8 < 4; k8++) {
                const int k = k8 * 8;
                uint32_t af[2][4], bf[8][2];
#pragma unroll
                for (int mi = 0; mi < 2; mi++) {
                    int r = wm + mi * 16 + (lane >> 2);
                    af[mi][0] = __float_as_uint(As[r    ][k +     (lane & 3)]);
                    af[mi][1] = __float_as_uint(As[r + 8][k +     (lane & 3)]);
                    af[mi][2] = __float_as_uint(As[r    ][k + 4 + (lane & 3)]);
                    af[mi][3] = __float_as_uint(As[r + 8][k + 4 + (lane & 3)]);
                }
#pragma unroll
                for (int ni = 0; ni < 8; ni++) {
                    int n = wn + ni * 8 + (lane >> 2);
                    bf[ni][0] = __float_as_uint(Bs[kc * 32 + k +     (lane & 3)][n]);
                    bf[ni][1] = __float_as_uint(Bs[kc * 32 + k + 4 + (lane & 3)][n]);
                }
#pragma unroll
                for (int mi = 0; mi < 2; mi++)
#pragma unroll
                    for (int ni = 0; ni < 8; ni++)
                        mma_tf32(acc[mi][ni], af[mi], bf[ni]);
            }
        }

        float* dst = (ot == 0 ? g_eq : (ot == 1 ? g_ek : g_v)) + (size_t)b * CT;
        if (ot == 2) {
#pragma unroll
            for (int mi = 0; mi < 2; mi++)
#pragma unroll
                for (int half = 0; half < 2; half++) {
                    int r = wm + mi * 16 + (lane >> 2) + half * 8;
#pragma unroll
                    for (int ni = 0; ni < 8; ni++)
                        *(float2*)(dst + (size_t)r * T_ + t0 + wn + ni * 8
                                   + 2 * (lane & 3)) =
                            make_float2(acc[mi][ni][half * 2],
                                        acc[mi][ni][half * 2 + 1]);
                }
        } else {
            __syncthreads();
            if (tid < 128) rsum[tid] = 0.f;
            __syncthreads();
#pragma unroll
            for (int mi = 0; mi < 2; mi++)
#pragma unroll
                for (int half = 0; half < 2; half++) {
                    int r = wm + mi * 16 + (lane >> 2) + half * 8;
                    float s = 0.f;
#pragma unroll
                    for (int ni = 0; ni < 8; ni++) {
                        float e0 = __expf(acc[mi][ni][half * 2]);
                        float e1 = __expf(acc[mi][ni][half * 2 + 1]);
                        s += e0 + e1;
                        *(float2*)(dst + (size_t)r * T_ + t0 + wn + ni * 8
                                   + 2 * (lane & 3)) = make_float2(e0, e1);
                    }
                    s += __shfl_xor_sync(0xffffffffu, s, 1);
                    s += __shfl_xor_sync(0xffffffffu, s, 2);
                    if ((lane & 3) == 0) atomicAdd(&rsum[r], s);
                }
            __syncthreads();
            float* S = (ot == 0 ? g_Sq : g_Sk) + b * C_;
            if (tid < 128) atomicAdd(&S[tid], rsum[tid]);
        }
    }

    // ---- fused ctx: re-stage this block's ek/v tiles (L2-hot) per head ------
    __syncthreads();                            // all q/k/v stores visible
    float (*ekh)[136] = (float(*)[136])dsm;     // reuse dead x-tile region
    float (*vh)[136]  = (float(*)[136])(dsm + 32 * 136);
    const float* EK = g_ek + (size_t)b * CT + t0;
    const float* VV = g_v  + (size_t)b * CT + t0;

    for (int h = 0; h < H_; h++) {
        for (int i = tid; i < D_ * D_; i += 256) cacc[i] = 0.f;
#pragma unroll
        for (int it = 0; it < 4; it++) {        // stage ek_h, v_h [32][128]
            int i = tid + it * 256, row = i >> 5, c4 = (i & 31) * 4;
            float4 kv = *(const float4*)(EK + (size_t)(h * 32 + row) * T_ + c4);
            float4 vv = *(const float4*)(VV + (size_t)(h * 32 + row) * T_ + c4);
            *(float4*)&ekh[row][c4] = make_float4(tf32r(kv.x), tf32r(kv.y),
                                                  tf32r(kv.z), tf32r(kv.w));
            *(float4*)&vh[row][c4]  = make_float4(tf32r(vv.x), tf32r(vv.y),
                                                  tf32r(vv.z), tf32r(vv.w));
        }
        __syncthreads();

        float a2[2][4][4];
#pragma unroll
        for (int mi = 0; mi < 2; mi++)
#pragma unroll
            for (int ni = 0; ni < 4; ni++)
#pragma unroll
                for (int r = 0; r < 4; r++) a2[mi][ni][r] = 0.f;
#pragma unroll
        for (int k8 = 0; k8 < 2; k8++) {        // warp K-slice: 16 t each
            const int kb = wid * 16 + k8 * 8;
            uint32_t af[2][4], bf[4][2];
#pragma unroll
            for (int mi = 0; mi < 2; mi++) {
                int r = mi * 16 + (lane >> 2);
                af[mi][0] = __float_as_uint(ekh[r    ][kb +     (lane & 3)]);
                af[mi][1] = __float_as_uint(ekh[r + 8][kb +     (lane & 3)]);
                af[mi][2] = __float_as_uint(ekh[r    ][kb + 4 + (lane & 3)]);
                af[mi][3] = __float_as_uint(ekh[r + 8][kb + 4 + (lane & 3)]);
            }
#pragma unroll
            for (int ni = 0; ni < 4; ni++) {
                int n = ni * 8 + (lane >> 2);
                bf[ni][0] = __float_as_uint(vh[n][kb +     (lane & 3)]);
                bf[ni][1] = __float_as_uint(vh[n][kb + 4 + (lane & 3)]);
            }
#pragma unroll
            for (int mi = 0; mi < 2; mi++)
#pragma unroll
                for (int ni = 0; ni < 4; ni++)
                    mma_tf32(a2[mi][ni], af[mi], bf[ni]);
        }
#pragma unroll
        for (int mi = 0; mi < 2; mi++)
#pragma unroll
            for (int ni = 0; ni < 4; ni++)
#pragma unroll
                for (int r = 0; r < 4; r++) {
                    int d = mi * 16 + (lane >> 2) + (r >> 1) * 8;
                    int e = ni * 8 + (lane & 3) * 2 + (r & 1);
                    atomicAdd(&cacc[d * D_ + e], a2[mi][ni][r]);
                }
        __syncthreads();
        float* Cp = g_ctx + (size_t)(b * H_ + h) * (D_ * D_);
        for (int i = tid; i < D_ * D_; i += 256) atomicAdd(&Cp[i], cacc[i]);
        __syncthreads();
    }
}

// ---------------- K2: out = (W_out x ctx') @ eq + bias; GN moments -----------
// SMEM: Ms [128][132] | Bs eq-chunk [32][136] (cf reuses Bs pre-GEMM)
#define OUT_SMEM ((128 * 132 + 32 * 136) * 4)

__global__ __launch_bounds__(256, 2) void k_out(const float* __restrict__ w_out,
                                                const float* __restrict__ b_out) {
    extern __shared__ float dsm[];
    float (*Ms)[132] = (float(*)[132])dsm;
    float (*Bs)[136] = (float(*)[136])(dsm + 128 * 132);
    float* cf        = (float*)Bs;
    const int b = blockIdx.y, t0 = blockIdx.x * 128;
    const int tid = threadIdx.x, lane = tid & 31, wid = tid >> 5;
    const int wm = (wid >> 1) * 32, wn = (wid & 1) * 64;
    const float scale = 0.17677669529663687f;  // 32^-0.5

    for (int i = tid; i < H_ * D_ * D_; i += 256) {
        int h = i >> 10, d = (i >> 5) & 31;
        float sk = g_Sk[b * C_ + h * D_ + d], sq = g_Sq[b * C_ + h * D_ + d];
        cf[i] = scale * g_ctx[b * (H_ * D_ * D_) + i] / (sk * sq);
    }
    __syncthreads();
    for (int i = tid; i < C_ * C_; i += 256) {
        int o = i >> 7, hd = i & 127, h = hd >> 5, d = hd & 31;
        const float* wr = w_out + o * C_ + h * D_;
        const float* cr = cf + (h * D_ + d) * D_;
        float s0 = 0, s1 = 0, s2 = 0, s3 = 0;
#pragma unroll
        for (int e = 0; e < 32; e += 4) {
            s0 = fmaf(wr[e    ], cr[e    ], s0);
            s1 = fmaf(wr[e + 1], cr[e + 1], s1);
            s2 = fmaf(wr[e + 2], cr[e + 2], s2);
            s3 = fmaf(wr[e + 3], cr[e + 3], s3);
        }
        Ms[o][hd] = tf32r((s0 + s1) + (s2 + s3));
    }

    const float* Bg = g_eq + (size_t)b * CT;
    float acc[2][8][4];
#pragma unroll
    for (int mi = 0; mi < 2; mi++)
#pragma unroll
        for (int ni = 0; ni < 8; ni++)
#pragma unroll
            for (int r = 0; r < 4; r++) acc[mi][ni][r] = 0.f;

    float4 bpre[4];
#pragma unroll
    for (int it = 0; it < 4; it++) {
        int idx = tid + it * 256, row = idx >> 5, c4 = idx & 31;
        bpre[it] = *(const float4*)(Bg + (size_t)row * T_ + t0 + c4 * 4);
    }
    for (int kc = 0; kc < 4; kc++) {
        __syncthreads();
#pragma unroll
        for (int it = 0; it < 4; it++) {
            int idx = tid + it * 256, row = idx >> 5, c4 = idx & 31;
            float4 v = bpre[it];
            *(float4*)&Bs[row][c4 * 4] = make_float4(tf32r(v.x), tf32r(v.y),
                                                     tf32r(v.z), tf32r(v.w));
        }
        __syncthreads();
        if (kc < 3) {
#pragma unroll
            for (int it = 0; it < 4; it++) {
                int idx = tid + it * 256, row = idx >> 5, c4 = idx & 31;
                bpre[it] = *(const float4*)(Bg + (size_t)((kc + 1) * 32 + row) * T_
                                            + t0 + c4 * 4);
            }
        }
#pragma unroll
        for (int k8 = 0; k8 < 4; k8++) {
            const int k = kc * 32 + k8 * 8, ks = k8 * 8;
            uint32_t af[2][4], bf[8][2];
#pragma unroll
            for (int mi = 0; mi < 2; mi++) {
                int r = wm + mi * 16 + (lane >> 2);
                af[mi][0] = __float_as_uint(Ms[r    ][k +     (lane & 3)]);
                af[mi][1] = __float_as_uint(Ms[r + 8][k +     (lane & 3)]);
                af[mi][2] = __float_as_uint(Ms[r    ][k + 4 + (lane & 3)]);
                af[mi][3] = __float_as_uint(Ms[r + 8][k + 4 + (lane & 3)]);
            }
#pragma unroll
            for (int ni = 0; ni < 8; ni++) {
                int n = wn + ni * 8 + (lane >> 2);
                bf[ni][0] = __float_as_uint(Bs[ks +     (lane & 3)][n]);
                bf[ni][1] = __float_as_uint(Bs[ks + 4 + (lane & 3)][n]);
            }
#pragma unroll
            for (int mi = 0; mi < 2; mi++)
#pragma unroll
                for (int ni = 0; ni < 8; ni++)
                    mma_tf32(acc[mi][ni], af[mi], bf[ni]);
        }
    }

    float* dst = g_op + (size_t)b * CT;
    float s1 = 0.f, s2 = 0.f;
#pragma unroll
    for (int mi = 0; mi < 2; mi++)
#pragma unroll
        for (int half = 0; half < 2; half++) {
            int r = wm + mi * 16 + (lane >> 2) + half * 8;
            float bo = __ldg(&b_out[r]);
#pragma unroll
            for (int ni = 0; ni < 8; ni++) {
                float v0 = acc[mi][ni][half * 2]     + bo;
                float v1 = acc[mi][ni][half * 2 + 1] + bo;
                s1 += v0 + v1;
                s2 = fmaf(v0, v0, s2); s2 = fmaf(v1, v1, s2);
                *(float2*)(dst + (size_t)r * T_ + t0 + wn + ni * 8
                           + 2 * (lane & 3)) = make_float2(v0, v1);
            }
        }
#pragma unroll
    for (int o = 16; o > 0; o >>= 1) {
        s1 += __shfl_down_sync(0xffffffffu, s1, o);
        s2 += __shfl_down_sync(0xffffffffu, s2, o);
    }
    if (lane == 0) {
        atomicAdd(&g_stats[b * 2 + 0], s1);
        atomicAdd(&g_stats[b * 2 + 1], s2);
    }
}

// ---------------- K3: GroupNorm finalize -------------------------------------
__global__ void k_norm(const float* __restrict__ gnw,
                       const float* __restrict__ gnb,
                       float* __restrict__ out) {
    int i4 = blockIdx.x * 256 + threadIdx.x;
    int e  = i4 * 4;
    int b  = e >> 21;
    int c  = (e >> 14) & 127;
    const float inv = 1.0f / (float)CT;
    float m    = g_stats[b * 2 + 0] * inv;
    float var  = g_stats[b * 2 + 1] * inv - m * m;
    float rstd = rsqrtf(var + 1e-5f);
    float w    = gnw[c] * rstd;
    float bias = gnb[c] - m * w;
    float4 v = *(const float4*)(g_op + e);
    v.x = v.x * w + bias; v.y = v.y * w + bias;
    v.z = v.z * w + bias; v.w = v.w * w + bias;
    *(float4*)(out + e) = v;
}

// ---------------- launch ------------------------------------------------------
extern "C" void kernel_launch(void* const* d_in, const int* in_sizes, int n_in,
                              void* d_out, int out_size)
{
    const float* x    = (const float*)d_in[0];
    const float* wqkv = (const float*)d_in[1];
    const float* wout = (const float*)d_in[2];
    const float* bout = (const float*)d_in[3];
    const float* gnw  = (const float*)d_in[4];
    const float* gnb  = (const float*)d_in[5];
    float* out = (float*)d_out;

    cudaFuncSetAttribute(k_qkv, cudaFuncAttributeMaxDynamicSharedMemorySize, QKV_SMEM);
    cudaFuncSetAttribute(k_out, cudaFuncAttributeMaxDynamicSharedMemorySize, OUT_SMEM);

    k_zero<<<256, 256>>>();
    k_qkv<<<dim3(T_ / 128, B_), 256, QKV_SMEM>>>(x, wqkv);
    k_out<<<dim3(T_ / 128, B_), 256, OUT_SMEM>>>(wout, bout);
    k_norm<<<32768, 256>>>(gnw, gnb, out);
}

// round 9
// speedup vs baseline: 5.0201x; 3.5104x over previous
#include <cuda_runtime.h>
#include <cuda_fp16.h>
#include <cstdint>

#define B_ 16
#define C_ 128
#define T_ 16384
#define H_ 4
#define D_ 32
#define CT (C_ * T_)

__device__ float  g_eq[B_ * CT];
__device__ __half g_ek[B_ * CT];
__device__ __half g_v [B_ * CT];
__device__ float  g_op[B_ * CT];
__device__ float  g_Sq[B_ * C_];
__device__ float  g_Sk[B_ * C_];
__device__ float  g_ctx[B_ * H_ * D_ * D_];
__device__ float  g_M[B_ * C_ * C_];
__device__ float  g_stats[B_ * 2];

__device__ __forceinline__ float tf32r(float x) {
    uint32_t y;
    asm("cvt.rna.tf32.f32 %0, %1;" : "=r"(y) : "f"(x));
    return __uint_as_float(y);
}
__device__ __forceinline__ void mma_tf32(float* d, const uint32_t* a, const uint32_t* b2) {
    asm volatile("mma.sync.aligned.m16n8k8.row.col.f32.tf32.tf32.f32 "
        "{%0,%1,%2,%3}, {%4,%5,%6,%7}, {%8,%9}, {%0,%1,%2,%3};"
        : "+f"(d[0]), "+f"(d[1]), "+f"(d[2]), "+f"(d[3])
        : "r"(a[0]), "r"(a[1]), "r"(a[2]), "r"(a[3]), "r"(b2[0]), "r"(b2[1]));
}
__device__ __forceinline__ void mma_f16(float* d, const uint32_t* a, const uint32_t* b2) {
    asm volatile("mma.sync.aligned.m16n8k16.row.col.f32.f16.f16.f32 "
        "{%0,%1,%2,%3}, {%4,%5,%6,%7}, {%8,%9}, {%0,%1,%2,%3};"
        : "+f"(d[0]), "+f"(d[1]), "+f"(d[2]), "+f"(d[3])
        : "r"(a[0]), "r"(a[1]), "r"(a[2]), "r"(a[3]), "r"(b2[0]), "r"(b2[1]));
}

// ---- 128x128 GEMM core used by k_out (R5/R6-proven, unchanged) --------------
__device__ __forceinline__ void gemm128(const float* __restrict__ Ag,
                                        const float* __restrict__ Bg, int t0,
                                        float acc[2][8][4],
                                        float (*As)[36], float (*Bs)[136]) {
    const int tid = threadIdx.x, lane = tid & 31, wid = tid >> 5;
    const int wm = (wid >> 1) * 32, wn = (wid & 1) * 64;
    float4 bpre[4];
#pragma unroll
    for (int it = 0; it < 4; it++) {
        int idx = tid + it * 256, row = idx >> 5, c4 = idx & 31;
        bpre[it] = *(const float4*)(Bg + (size_t)row * T_ + t0 + c4 * 4);
    }
    for (int kc = 0; kc < 4; kc++) {
        __syncthreads();
#pragma unroll
        for (int it = 0; it < 4; it++) {
            int idx = tid + it * 256, row = idx >> 3, c4 = idx & 7;
            float4 v = *(const float4*)(Ag + row * 128 + kc * 32 + c4 * 4);
            float4 w = make_float4(tf32r(v.x), tf32r(v.y), tf32r(v.z), tf32r(v.w));
            *(float4*)&As[row][c4 * 4] = w;
        }
#pragma unroll
        for (int it = 0; it < 4; it++) {
            int idx = tid + it * 256, row = idx >> 5, c4 = idx & 31;
            float4 v = bpre[it];
            float4 w = make_float4(tf32r(v.x), tf32r(v.y), tf32r(v.z), tf32r(v.w));
            *(float4*)&Bs[row][c4 * 4] = w;
        }
        __syncthreads();
        if (kc < 3) {
#pragma unroll
            for (int it = 0; it < 4; it++) {
                int idx = tid + it * 256, row = idx >> 5, c4 = idx & 31;
                bpre[it] = *(const float4*)(Bg + (size_t)((kc + 1) * 32 + row) * T_
                                            + t0 + c4 * 4);
            }
        }
#pragma unroll
        for (int k8 = 0; k8 < 4; k8++) {
            const int k = k8 * 8;
            uint32_t af[2][4], bf[8][2];
#pragma unroll
            for (int mi = 0; mi < 2; mi++) {
                int r = wm + mi * 16 + (lane >> 2);
                af[mi][0] = __float_as_uint(As[r    ][k +     (lane & 3)]);
                af[mi][1] = __float_as_uint(As[r + 8][k +     (lane & 3)]);
                af[mi][2] = __float_as_uint(As[r    ][k + 4 + (lane & 3)]);
                af[mi][3] = __float_as_uint(As[r + 8][k + 4 + (lane & 3)]);
            }
#pragma unroll
            for (int ni = 0; ni < 8; ni++) {
                int n = wn + ni * 8 + (lane >> 2);
                bf[ni][0] = __float_as_uint(Bs[k +     (lane & 3)][n]);
                bf[ni][1] = __float_as_uint(Bs[k + 4 + (lane & 3)][n]);
            }
#pragma unroll
            for (int mi = 0; mi < 2; mi++)
#pragma unroll
                for (int ni = 0; ni < 8; ni++)
                    mma_tf32(acc[mi][ni], af[mi], bf[ni]);
        }
    }
}

// ---------------- K0: zero ---------------------------------------------------
__global__ void k_zero() {
    int i = blockIdx.x * 256 + threadIdx.x;
    if (i < B_ * C_)           { g_Sq[i] = 0.f; g_Sk[i] = 0.f; }
    if (i < B_ * H_ * D_ * D_) g_ctx[i] = 0.f;
    if (i < B_ * 2)            g_stats[i] = 0.f;
}

// ---------------- K1: fused QKV GEMM (R6-proven; only k/v stores -> half) ----
#define QKV_SMEM ((128 * 136 + 128 * 36 + 128) * 4)

__global__ __launch_bounds__(256, 2) void k_qkv(const float* __restrict__ x,
                                                const float* __restrict__ wqkv) {
    extern __shared__ float dsm[];
    float (*Bs)[136] = (float(*)[136])dsm;
    float (*As)[36]  = (float(*)[36])(dsm + 128 * 136);
    float* rsum      = dsm + 128 * 136 + 128 * 36;
    const int b = blockIdx.y, t0 = blockIdx.x * 128;
    const int tid = threadIdx.x, lane = tid & 31, wid = tid >> 5;
    const int wm = (wid >> 1) * 32, wn = (wid & 1) * 64;

    const float* xb = x + (size_t)b * CT;
#pragma unroll
    for (int it = 0; it < 16; it++) {
        int idx = tid + it * 256, row = idx >> 5, c4 = (idx & 31) * 4;
        float4 v = *(const float4*)(xb + (size_t)row * T_ + t0 + c4);
        *(float4*)&Bs[row][c4] = make_float4(tf32r(v.x), tf32r(v.y),
                                             tf32r(v.z), tf32r(v.w));
    }

    for (int ot = 0; ot < 3; ot++) {
        float acc[2][8][4];
#pragma unroll
        for (int mi = 0; mi < 2; mi++)
#pragma unroll
            for (int ni = 0; ni < 8; ni++)
#pragma unroll
                for (int r = 0; r < 4; r++) acc[mi][ni][r] = 0.f;

        for (int kc = 0; kc < 4; kc++) {
            __syncthreads();
#pragma unroll
            for (int it = 0; it < 4; it++) {
                int idx = tid + it * 256, row = idx >> 3, c4 = (idx & 7) * 4;
                float4 v = *(const float4*)(wqkv + (size_t)(ot * 128 + row) * 128
                                            + kc * 32 + c4);
                *(float4*)&As[row][c4] = make_float4(tf32r(v.x), tf32r(v.y),
                                                     tf32r(v.z), tf32r(v.w));
            }
            __syncthreads();
#pragma unroll
            for (int k8 = 0; k8 < 4; k8++) {
                const int k = k8 * 8;
                uint32_t af[2][4], bf[8][2];
#pragma unroll
                for (int mi = 0; mi < 2; mi++) {
                    int r = wm + mi * 16 + (lane >> 2);
                    af[mi][0] = __float_as_uint(As[r    ][k +     (lane & 3)]);
                    af[mi][1] = __float_as_uint(As[r + 8][k +     (lane & 3)]);
                    af[mi][2] = __float_as_uint(As[r    ][k + 4 + (lane & 3)]);
                    af[mi][3] = __float_as_uint(As[r + 8][k + 4 + (lane & 3)]);
                }
#pragma unroll
                for (int ni = 0; ni < 8; ni++) {
                    int n = wn + ni * 8 + (lane >> 2);
                    bf[ni][0] = __float_as_uint(Bs[kc * 32 + k +     (lane & 3)][n]);
                    bf[ni][1] = __float_as_uint(Bs[kc * 32 + k + 4 + (lane & 3)][n]);
                }
#pragma unroll
                for (int mi = 0; mi < 2; mi++)
#pragma unroll
                    for (int ni = 0; ni < 8; ni++)
                        mma_tf32(acc[mi][ni], af[mi], bf[ni]);
            }
        }

        if (ot == 2) {                       // v: store half
            __half* dst = g_v + (size_t)b * CT;
#pragma unroll
            for (int mi = 0; mi < 2; mi++)
#pragma unroll
                for (int half = 0; half < 2; half++) {
                    int r = wm + mi * 16 + (lane >> 2) + half * 8;
#pragma unroll
                    for (int ni = 0; ni < 8; ni++)
                        *(__half2*)(dst + (size_t)r * T_ + t0 + wn + ni * 8
                                    + 2 * (lane & 3)) =
                            __floats2half2_rn(acc[mi][ni][half * 2],
                                              acc[mi][ni][half * 2 + 1]);
                }
        } else {                             // q (float) / k (half) + row sums
            __syncthreads();
            if (tid < 128) rsum[tid] = 0.f;
            __syncthreads();
            float*  dq = g_eq + (size_t)b * CT;
            __half* dk = g_ek + (size_t)b * CT;
#pragma unroll
            for (int mi = 0; mi < 2; mi++)
#pragma unroll
                for (int half = 0; half < 2; half++) {
                    int r = wm + mi * 16 + (lane >> 2) + half * 8;
                    float s = 0.f;
#pragma unroll
                    for (int ni = 0; ni < 8; ni++) {
                        float e0 = __expf(acc[mi][ni][half * 2]);
                        float e1 = __expf(acc[mi][ni][half * 2 + 1]);
                        s += e0 + e1;
                        size_t off = (size_t)r * T_ + t0 + wn + ni * 8
                                     + 2 * (lane & 3);
                        if (ot == 0) *(float2*)(dq + off) = make_float2(e0, e1);
                        else         *(__half2*)(dk + off) = __floats2half2_rn(e0, e1);
                    }
                    s += __shfl_xor_sync(0xffffffffu, s, 1);
                    s += __shfl_xor_sync(0xffffffffu, s, 2);
                    if ((lane & 3) == 0) atomicAdd(&rsum[r], s);
                }
            __syncthreads();
            float* S = (ot == 0 ? g_Sq : g_Sk) + b * C_;
            if (tid < 128) atomicAdd(&S[tid], rsum[tid]);
        }
    }
}

// ---------------- K2: ctx via fp16 tensor cores ------------------------------
// ctx[d,e] = sum_t ek[d,t]*v[e,t];  A=ek (row=d,k=t), B=v (col=e,k=t)
__global__ __launch_bounds__(256) void k_ctx() {
    const int b = blockIdx.z, h = blockIdx.y, sp = blockIdx.x;
    const __half* K = g_ek + (size_t)(b * C_ + h * D_) * T_;
    const __half* V = g_v  + (size_t)(b * C_ + h * D_) * T_;
    __shared__ __half ekh[32][136];     // 128-t chunk, pad to 272B rows
    __shared__ __half vh [32][136];
    __shared__ float cacc[D_ * D_];
    const int tid = threadIdx.x, lane = tid & 31, wid = tid >> 5;
    const int g = lane >> 2, c2 = (lane & 3) * 2;
    const int kb = wid * 16;            // warp's 16-wide t-slice in chunk

    for (int i = tid; i < D_ * D_; i += 256) cacc[i] = 0.f;

    float acc[2][4][4];
#pragma unroll
    for (int mi = 0; mi < 2; mi++)
#pragma unroll
        for (int ni = 0; ni < 4; ni++)
#pragma unroll
            for (int r = 0; r < 4; r++) acc[mi][ni][r] = 0.f;

    for (int n0 = sp * 512; n0 < sp * 512 + 512; n0 += 128) {
        // stage 32 rows x 128 halves each (uint4 = 8 halves)
        for (int i = tid; i < 512; i += 256) {
            int row = i >> 4, c8 = (i & 15) * 8;
            *(uint4*)&ekh[row][c8] = *(const uint4*)(K + (size_t)row * T_ + n0 + c8);
            *(uint4*)&vh [row][c8] = *(const uint4*)(V + (size_t)row * T_ + n0 + c8);
        }
        __syncthreads();
        uint32_t af[2][4], bf[4][2];
#pragma unroll
        for (int mi = 0; mi < 2; mi++) {
            int r = mi * 16 + g;
            af[mi][0] = *(const uint32_t*)&ekh[r    ][kb +     c2];
            af[mi][1] = *(const uint32_t*)&ekh[r + 8][kb +     c2];
            af[mi][2] = *(const uint32_t*)&ekh[r    ][kb + 8 + c2];
            af[mi][3] = *(const uint32_t*)&ekh[r + 8][kb + 8 + c2];
        }
#pragma unroll
        for (int ni = 0; ni < 4; ni++) {
            int n = ni * 8 + g;
            bf[ni][0] = *(const uint32_t*)&vh[n][kb +     c2];
            bf[ni][1] = *(const uint32_t*)&vh[n][kb + 8 + c2];
        }
#pragma unroll
        for (int mi = 0; mi < 2; mi++)
#pragma unroll
            for (int ni = 0; ni < 4; ni++)
                mma_f16(acc[mi][ni], af[mi], bf[ni]);
        __syncthreads();
    }
#pragma unroll
    for (int mi = 0; mi < 2; mi++)
#pragma unroll
        for (int ni = 0; ni < 4; ni++)
#pragma unroll
            for (int r = 0; r < 4; r++) {
                int d = mi * 16 + g + (r >> 1) * 8;
                int e = ni * 8 + c2 + (r & 1);
                atomicAdd(&cacc[d * D_ + e], acc[mi][ni][r]);
            }
    __syncthreads();
    float* Cp = g_ctx + (size_t)(b * H_ + h) * (D_ * D_);
    for (int i = tid; i < D_ * D_; i += 256) atomicAdd(&Cp[i], cacc[i]);
}

// ---------------- K3: fused M = W_out x (scaled ctx) -------------------------
__global__ __launch_bounds__(256) void k_M(const float* __restrict__ w_out) {
    const int oseg = blockIdx.x, b = blockIdx.y;
    __shared__ float cf[H_ * D_ * D_];
    const int tid = threadIdx.x;
    const float scale = 0.17677669529663687f;  // 32^-0.5
    for (int i = tid; i < H_ * D_ * D_; i += 256) {
        int h = i >> 10, d = (i >> 5) & 31;
        float sk = g_Sk[b * C_ + h * D_ + d], sq = g_Sq[b * C_ + h * D_ + d];
        cf[i] = scale * g_ctx[b * (H_ * D_ * D_) + i] / (sk * sq);
    }
    __syncthreads();
    for (int i = tid; i < 16 * C_; i += 256) {
        int o = oseg * 16 + (i >> 7), hd = i & 127;
        int h = hd >> 5, d = hd & 31;
        const float* wr = w_out + o * C_ + h * D_;
        const float* cr = cf + (h * D_ + d) * D_;
        float s = 0.f;
#pragma unroll
        for (int e = 0; e < 32; e++) s = fmaf(wr[e], cr[e], s);
        g_M[b * (C_ * C_) + o * C_ + hd] = s;
    }
}

// ---------------- K4: out = M @ eq + bias; GN moments ------------------------
__global__ __launch_bounds__(256, 2) void k_out(const float* __restrict__ b_out) {
    __shared__ __align__(16) float As[128][36];
    __shared__ __align__(16) float Bs[32][136];
    const int b = blockIdx.y, t0 = blockIdx.x * 128;
    const int tid = threadIdx.x, lane = tid & 31, wid = tid >> 5;

    float acc[2][8][4];
#pragma unroll
    for (int mi = 0; mi < 2; mi++)
#pragma unroll
        for (int ni = 0; ni < 8; ni++)
#pragma unroll
            for (int r = 0; r < 4; r++) acc[mi][ni][r] = 0.f;

    gemm128(g_M + b * 128 * 128, g_eq + (size_t)b * CT, t0, acc, As, Bs);

    const int wm = (wid >> 1) * 32, wn = (wid & 1) * 64;
    float* dst = g_op + (size_t)b * CT;
    float s1 = 0.f, s2 = 0.f;
#pragma unroll
    for (int mi = 0; mi < 2; mi++)
#pragma unroll
        for (int half = 0; half < 2; half++) {
            int r = wm + mi * 16 + (lane >> 2) + half * 8;
            float bo = __ldg(&b_out[r]);
#pragma unroll
            for (int ni = 0; ni < 8; ni++) {
                float v0 = acc[mi][ni][half * 2]     + bo;
                float v1 = acc[mi][ni][half * 2 + 1] + bo;
                s1 += v0 + v1;
                s2 = fmaf(v0, v0, s2); s2 = fmaf(v1, v1, s2);
                *(float2*)(dst + (size_t)r * T_ + t0 + wn + ni * 8
                           + 2 * (lane & 3)) = make_float2(v0, v1);
            }
        }
#pragma unroll
    for (int o = 16; o > 0; o >>= 1) {
        s1 += __shfl_down_sync(0xffffffffu, s1, o);
        s2 += __shfl_down_sync(0xffffffffu, s2, o);
    }
    if (lane == 0) {
        atomicAdd(&g_stats[b * 2 + 0], s1);
        atomicAdd(&g_stats[b * 2 + 1], s2);
    }
}

// ---------------- K5: GroupNorm finalize -------------------------------------
__global__ void k_norm(const float* __restrict__ gnw,
                       const float* __restrict__ gnb,
                       float* __restrict__ out) {
    int i4 = blockIdx.x * 256 + threadIdx.x;
    int e  = i4 * 4;
    int b  = e >> 21;
    int c  = (e >> 14) & 127;
    const float inv = 1.0f / (float)CT;
    float m    = g_stats[b * 2 + 0] * inv;
    float var  = g_stats[b * 2 + 1] * inv - m * m;
    float rstd = rsqrtf(var + 1e-5f);
    float w    = gnw[c] * rstd;
    float bias = gnb[c] - m * w;
    float4 v = *(const float4*)(g_op + e);
    v.x = v.x * w + bias; v.y = v.y * w + bias;
    v.z = v.z * w + bias; v.w = v.w * w + bias;
    *(float4*)(out + e) = v;
}

// ---------------- launch ------------------------------------------------------
extern "C" void kernel_launch(void* const* d_in, const int* in_sizes, int n_in,
                              void* d_out, int out_size)
{
    const float* x    = (const float*)d_in[0];
    const float* wqkv = (const float*)d_in[1];
    const float* wout = (const float*)d_in[2];
    const float* bout = (const float*)d_in[3];
    const float* gnw  = (const float*)d_in[4];
    const float* gnb  = (const float*)d_in[5];
    float* out = (float*)d_out;

    cudaFuncSetAttribute(k_qkv, cudaFuncAttributeMaxDynamicSharedMemorySize, QKV_SMEM);

    k_zero<<<256, 256>>>();
    k_qkv<<<dim3(T_ / 128, B_), 256, QKV_SMEM>>>(x, wqkv);
    k_ctx<<<dim3(32, H_, B_), 256>>>();
    k_M<<<dim3(8, B_), 256>>>(wout);
    k_out<<<dim3(T_ / 128, B_), 256>>>(bout);
    k_norm<<<32768, 256>>>(gnw, gnb, out);
}

// round 10
// speedup vs baseline: 5.1116x; 1.0182x over previous
#include <cuda_runtime.h>
#include <cuda_fp16.h>
#include <cstdint>

#define B_ 16
#define C_ 128
#define T_ 16384
#define H_ 4
#define D_ 32
#define CT (C_ * T_)

__device__ __half g_eq[B_ * CT];
__device__ __half g_ek[B_ * CT];
__device__ __half g_v [B_ * CT];
__device__ __half g_op[B_ * CT];
__device__ float  g_Sq[B_ * C_];
__device__ float  g_Sk[B_ * C_];
__device__ float  g_ctx[B_ * H_ * D_ * D_];
__device__ float  g_M[B_ * C_ * C_];
__device__ float  g_stats[B_ * 2];

__device__ __forceinline__ float tf32r(float x) {
    uint32_t y;
    asm("cvt.rna.tf32.f32 %0, %1;" : "=r"(y) : "f"(x));
    return __uint_as_float(y);
}
__device__ __forceinline__ void mma_tf32(float* d, const uint32_t* a, const uint32_t* b2) {
    asm volatile("mma.sync.aligned.m16n8k8.row.col.f32.tf32.tf32.f32 "
        "{%0,%1,%2,%3}, {%4,%5,%6,%7}, {%8,%9}, {%0,%1,%2,%3};"
        : "+f"(d[0]), "+f"(d[1]), "+f"(d[2]), "+f"(d[3])
        : "r"(a[0]), "r"(a[1]), "r"(a[2]), "r"(a[3]), "r"(b2[0]), "r"(b2[1]));
}
__device__ __forceinline__ void mma_f16(float* d, const uint32_t* a, const uint32_t* b2) {
    asm volatile("mma.sync.aligned.m16n8k16.row.col.f32.f16.f16.f32 "
        "{%0,%1,%2,%3}, {%4,%5,%6,%7}, {%8,%9}, {%0,%1,%2,%3};"
        : "+f"(d[0]), "+f"(d[1]), "+f"(d[2]), "+f"(d[3])
        : "r"(a[0]), "r"(a[1]), "r"(a[2]), "r"(a[3]), "r"(b2[0]), "r"(b2[1]));
}

// ---------------- K0: zero ---------------------------------------------------
__global__ void k_zero() {
    int i = blockIdx.x * 256 + threadIdx.x;
    if (i < B_ * C_)           { g_Sq[i] = 0.f; g_Sk[i] = 0.f; }
    if (i < B_ * H_ * D_ * D_) g_ctx[i] = 0.f;
    if (i < B_ * 2)            g_stats[i] = 0.f;
}

// ---------------- K1: fused QKV GEMM (q/k/v all stored fp16) -----------------
#define QKV_SMEM ((128 * 136 + 128 * 36 + 128) * 4)

__global__ __launch_bounds__(256, 2) void k_qkv(const float* __restrict__ x,
                                                const float* __restrict__ wqkv) {
    extern __shared__ float dsm[];
    float (*Bs)[136] = (float(*)[136])dsm;
    float (*As)[36]  = (float(*)[36])(dsm + 128 * 136);
    float* rsum      = dsm + 128 * 136 + 128 * 36;
    const int b = blockIdx.y, t0 = blockIdx.x * 128;
    const int tid = threadIdx.x, lane = tid & 31, wid = tid >> 5;
    const int wm = (wid >> 1) * 32, wn = (wid & 1) * 64;

    const float* xb = x + (size_t)b * CT;
#pragma unroll
    for (int it = 0; it < 16; it++) {
        int idx = tid + it * 256, row = idx >> 5, c4 = (idx & 31) * 4;
        float4 v = *(const float4*)(xb + (size_t)row * T_ + t0 + c4);
        *(float4*)&Bs[row][c4] = make_float4(tf32r(v.x), tf32r(v.y),
                                             tf32r(v.z), tf32r(v.w));
    }

    for (int ot = 0; ot < 3; ot++) {
        float acc[2][8][4];
#pragma unroll
        for (int mi = 0; mi < 2; mi++)
#pragma unroll
            for (int ni = 0; ni < 8; ni++)
#pragma unroll
                for (int r = 0; r < 4; r++) acc[mi][ni][r] = 0.f;

        for (int kc = 0; kc < 4; kc++) {
            __syncthreads();
#pragma unroll
            for (int it = 0; it < 4; it++) {
                int idx = tid + it * 256, row = idx >> 3, c4 = (idx & 7) * 4;
                float4 v = *(const float4*)(wqkv + (size_t)(ot * 128 + row) * 128
                                            + kc * 32 + c4);
                *(float4*)&As[row][c4] = make_float4(tf32r(v.x), tf32r(v.y),
                                                     tf32r(v.z), tf32r(v.w));
            }
            __syncthreads();
#pragma unroll
            for (int k8 = 0; k8 < 4; k8++) {
                const int k = k8 * 8;
                uint32_t af[2][4], bf[8][2];
#pragma unroll
                for (int mi = 0; mi < 2; mi++) {
                    int r = wm + mi * 16 + (lane >> 2);
                    af[mi][0] = __float_as_uint(As[r    ][k +     (lane & 3)]);
                    af[mi][1] = __float_as_uint(As[r + 8][k +     (lane & 3)]);
                    af[mi][2] = __float_as_uint(As[r    ][k + 4 + (lane & 3)]);
                    af[mi][3] = __float_as_uint(As[r + 8][k + 4 + (lane & 3)]);
                }
#pragma unroll
                for (int ni = 0; ni < 8; ni++) {
                    int n = wn + ni * 8 + (lane >> 2);
                    bf[ni][0] = __float_as_uint(Bs[kc * 32 + k +     (lane & 3)][n]);
                    bf[ni][1] = __float_as_uint(Bs[kc * 32 + k + 4 + (lane & 3)][n]);
                }
#pragma unroll
                for (int mi = 0; mi < 2; mi++)
#pragma unroll
                    for (int ni = 0; ni < 8; ni++)
                        mma_tf32(acc[mi][ni], af[mi], bf[ni]);
            }
        }

        if (ot == 2) {                       // v: store half
            __half* dst = g_v + (size_t)b * CT;
#pragma unroll
            for (int mi = 0; mi < 2; mi++)
#pragma unroll
                for (int half = 0; half < 2; half++) {
                    int r = wm + mi * 16 + (lane >> 2) + half * 8;
#pragma unroll
                    for (int ni = 0; ni < 8; ni++)
                        *(__half2*)(dst + (size_t)r * T_ + t0 + wn + ni * 8
                                    + 2 * (lane & 3)) =
                            __floats2half2_rn(acc[mi][ni][half * 2],
                                              acc[mi][ni][half * 2 + 1]);
                }
        } else {                             // q/k: exp -> half, fp32 row sums
            __syncthreads();
            if (tid < 128) rsum[tid] = 0.f;
            __syncthreads();
            __half* dst = (ot == 0 ? g_eq : g_ek) + (size_t)b * CT;
#pragma unroll
            for (int mi = 0; mi < 2; mi++)
#pragma unroll
                for (int half = 0; half < 2; half++) {
                    int r = wm + mi * 16 + (lane >> 2) + half * 8;
                    float s = 0.f;
#pragma unroll
                    for (int ni = 0; ni < 8; ni++) {
                        float e0 = __expf(acc[mi][ni][half * 2]);
                        float e1 = __expf(acc[mi][ni][half * 2 + 1]);
                        s += e0 + e1;
                        *(__half2*)(dst + (size_t)r * T_ + t0 + wn + ni * 8
                                    + 2 * (lane & 3)) = __floats2half2_rn(e0, e1);
                    }
                    s += __shfl_xor_sync(0xffffffffu, s, 1);
                    s += __shfl_xor_sync(0xffffffffu, s, 2);
                    if ((lane & 3) == 0) atomicAdd(&rsum[r], s);
                }
            __syncthreads();
            float* S = (ot == 0 ? g_Sq : g_Sk) + b * C_;
            if (tid < 128) atomicAdd(&S[tid], rsum[tid]);
        }
    }
}

// ---------------- K2: ctx via fp16 tensor cores (R9-proven) ------------------
__global__ __launch_bounds__(256) void k_ctx() {
    const int b = blockIdx.z, h = blockIdx.y, sp = blockIdx.x;
    const __half* K = g_ek + (size_t)(b * C_ + h * D_) * T_;
    const __half* V = g_v  + (size_t)(b * C_ + h * D_) * T_;
    __shared__ __half ekh[32][136];
    __shared__ __half vh [32][136];
    __shared__ float cacc[D_ * D_];
    const int tid = threadIdx.x, lane = tid & 31, wid = tid >> 5;
    const int g = lane >> 2, c2 = (lane & 3) * 2;
    const int kb = wid * 16;

    for (int i = tid; i < D_ * D_; i += 256) cacc[i] = 0.f;

    float acc[2][4][4];
#pragma unroll
    for (int mi = 0; mi < 2; mi++)
#pragma unroll
        for (int ni = 0; ni < 4; ni++)
#pragma unroll
            for (int r = 0; r < 4; r++) acc[mi][ni][r] = 0.f;

    for (int n0 = sp * 512; n0 < sp * 512 + 512; n0 += 128) {
        for (int i = tid; i < 512; i += 256) {
            int row = i >> 4, c8 = (i & 15) * 8;
            *(uint4*)&ekh[row][c8] = *(const uint4*)(K + (size_t)row * T_ + n0 + c8);
            *(uint4*)&vh [row][c8] = *(const uint4*)(V + (size_t)row * T_ + n0 + c8);
        }
        __syncthreads();
        uint32_t af[2][4], bf[4][2];
#pragma unroll
        for (int mi = 0; mi < 2; mi++) {
            int r = mi * 16 + g;
            af[mi][0] = *(const uint32_t*)&ekh[r    ][kb +     c2];
            af[mi][1] = *(const uint32_t*)&ekh[r + 8][kb +     c2];
            af[mi][2] = *(const uint32_t*)&ekh[r    ][kb + 8 + c2];
            af[mi][3] = *(const uint32_t*)&ekh[r + 8][kb + 8 + c2];
        }
#pragma unroll
        for (int ni = 0; ni < 4; ni++) {
            int n = ni * 8 + g;
            bf[ni][0] = *(const uint32_t*)&vh[n][kb +     c2];
            bf[ni][1] = *(const uint32_t*)&vh[n][kb + 8 + c2];
        }
#pragma unroll
        for (int mi = 0; mi < 2; mi++)
#pragma unroll
            for (int ni = 0; ni < 4; ni++)
                mma_f16(acc[mi][ni], af[mi], bf[ni]);
        __syncthreads();
    }
#pragma unroll
    for (int mi = 0; mi < 2; mi++)
#pragma unroll
        for (int ni = 0; ni < 4; ni++)
#pragma unroll
            for (int r = 0; r < 4; r++) {
                int d = mi * 16 + g + (r >> 1) * 8;
                int e = ni * 8 + c2 + (r & 1);
                atomicAdd(&cacc[d * D_ + e], acc[mi][ni][r]);
            }
    __syncthreads();
    float* Cp = g_ctx + (size_t)(b * H_ + h) * (D_ * D_);
    for (int i = tid; i < D_ * D_; i += 256) atomicAdd(&Cp[i], cacc[i]);
}

// ---------------- K3: fused M = W_out x (scaled ctx), conflict-free ----------
__global__ __launch_bounds__(256) void k_M(const float* __restrict__ w_out) {
    const int oseg = blockIdx.x, b = blockIdx.y;
    __shared__ float cf[H_ * D_ * 33];          // pad 33: stride-33 rows
    const int tid = threadIdx.x;
    const float scale = 0.17677669529663687f;  // 32^-0.5
    for (int i = tid; i < H_ * D_ * D_; i += 256) {
        int h = i >> 10, d = (i >> 5) & 31, e = i & 31;
        float sk = g_Sk[b * C_ + h * D_ + d], sq = g_Sq[b * C_ + h * D_ + d];
        cf[(h * D_ + d) * 33 + e] =
            scale * g_ctx[b * (H_ * D_ * D_) + i] / (sk * sq);
    }
    __syncthreads();
    for (int i = tid; i < 16 * C_; i += 256) {
        int o = oseg * 16 + (i >> 7), hd = i & 127;
        int h = hd >> 5, d = hd & 31;
        const float* wr = w_out + o * C_ + h * D_;
        const float* cr = cf + (h * D_ + d) * 33;
        float s = 0.f;
#pragma unroll
        for (int e = 0; e < 32; e++) s = fmaf(wr[e], cr[e], s);
        g_M[b * (C_ * C_) + o * C_ + hd] = s;
    }
}

// ---------------- K4: out = M @ eq + bias; GN moments; store fp16 ------------
__global__ __launch_bounds__(256, 2) void k_out(const float* __restrict__ b_out) {
    __shared__ __align__(16) float As[128][36];
    __shared__ __align__(16) float Bs[32][136];
    const int b = blockIdx.y, t0 = blockIdx.x * 128;
    const int tid = threadIdx.x, lane = tid & 31, wid = tid >> 5;
    const int wm = (wid >> 1) * 32, wn = (wid & 1) * 64;

    const float* Ag = g_M + b * 128 * 128;
    const __half* Bg = g_eq + (size_t)b * CT;

    float acc[2][8][4];
#pragma unroll
    for (int mi = 0; mi < 2; mi++)
#pragma unroll
        for (int ni = 0; ni < 8; ni++)
#pragma unroll
            for (int r = 0; r < 4; r++) acc[mi][ni][r] = 0.f;

    uint4 bpre[2];
#pragma unroll
    for (int it = 0; it < 2; it++) {
        int i = tid + it * 256, row = i >> 4, c8 = (i & 15) * 8;
        bpre[it] = *(const uint4*)(Bg + (size_t)row * T_ + t0 + c8);
    }
    for (int kc = 0; kc < 4; kc++) {
        __syncthreads();
#pragma unroll
        for (int it = 0; it < 4; it++) {            // stage M chunk (tf32)
            int idx = tid + it * 256, row = idx >> 3, c4 = (idx & 7) * 4;
            float4 v = *(const float4*)(Ag + row * 128 + kc * 32 + c4);
            *(float4*)&As[row][c4] = make_float4(tf32r(v.x), tf32r(v.y),
                                                 tf32r(v.z), tf32r(v.w));
        }
#pragma unroll
        for (int it = 0; it < 2; it++) {            // stage eq chunk half->f32
            int i = tid + it * 256, row = i >> 4, c8 = (i & 15) * 8;
            const __half2* hp = (const __half2*)&bpre[it];
#pragma unroll
            for (int q = 0; q < 4; q++) {
                float2 f = __half22float2(hp[q]);
                Bs[row][c8 + 2 * q]     = f.x;      // fp16 exactly representable
                Bs[row][c8 + 2 * q + 1] = f.y;     //   in tf32 -> no re-round
            }
        }
        __syncthreads();
        if (kc < 3) {
#pragma unroll
            for (int it = 0; it < 2; it++) {
                int i = tid + it * 256, row = i >> 4, c8 = (i & 15) * 8;
                bpre[it] = *(const uint4*)(Bg + (size_t)((kc + 1) * 32 + row) * T_
                                           + t0 + c8);
            }
        }
#pragma unroll
        for (int k8 = 0; k8 < 4; k8++) {
            const int k = kc * 32 + k8 * 8, ks = k8 * 8;
            uint32_t af[2][4], bf[8][2];
#pragma unroll
            for (int mi = 0; mi < 2; mi++) {
                int r = wm + mi * 16 + (lane >> 2);
                af[mi][0] = __float_as_uint(As[r    ][ks +     (lane & 3)]);
                af[mi][1] = __float_as_uint(As[r + 8][ks +     (lane & 3)]);
                af[mi][2] = __float_as_uint(As[r    ][ks + 4 + (lane & 3)]);
                af[mi][3] = __float_as_uint(As[r + 8][ks + 4 + (lane & 3)]);
            }
            (void)k;
#pragma unroll
            for (int ni = 0; ni < 8; ni++) {
                int n = wn + ni * 8 + (lane >> 2);
                bf[ni][0] = __float_as_uint(Bs[ks +     (lane & 3)][n]);
                bf[ni][1] = __float_as_uint(Bs[ks + 4 + (lane & 3)][n]);
            }
#pragma unroll
            for (int mi = 0; mi < 2; mi++)
#pragma unroll
                for (int ni = 0; ni < 8; ni++)
                    mma_tf32(acc[mi][ni], af[mi], bf[ni]);
        }
    }

    __half* dst = g_op + (size_t)b * CT;
    float s1 = 0.f, s2 = 0.f;
#pragma unroll
    for (int mi = 0; mi < 2; mi++)
#pragma unroll
        for (int half = 0; half < 2; half++) {
            int r = wm + mi * 16 + (lane >> 2) + half * 8;
            float bo = __ldg(&b_out[r]);
#pragma unroll
            for (int ni = 0; ni < 8; ni++) {
                float v0 = acc[mi][ni][half * 2]     + bo;
                float v1 = acc[mi][ni][half * 2 + 1] + bo;
                s1 += v0 + v1;
                s2 = fmaf(v0, v0, s2); s2 = fmaf(v1, v1, s2);
                *(__half2*)(dst + (size_t)r * T_ + t0 + wn + ni * 8
                            + 2 * (lane & 3)) = __floats2half2_rn(v0, v1);
            }
        }
#pragma unroll
    for (int o = 16; o > 0; o >>= 1) {
        s1 += __shfl_down_sync(0xffffffffu, s1, o);
        s2 += __shfl_down_sync(0xffffffffu, s2, o);
    }
    if (lane == 0) {
        atomicAdd(&g_stats[b * 2 + 0], s1);
        atomicAdd(&g_stats[b * 2 + 1], s2);
    }
}

// ---------------- K5: GroupNorm finalize (reads fp16 op) ---------------------
__global__ void k_norm(const float* __restrict__ gnw,
                       const float* __restrict__ gnb,
                       float* __restrict__ out) {
    int i4 = blockIdx.x * 256 + threadIdx.x;
    int e  = i4 * 4;
    int b  = e >> 21;
    int c  = (e >> 14) & 127;
    const float inv = 1.0f / (float)CT;
    float m    = g_stats[b * 2 + 0] * inv;
    float var  = g_stats[b * 2 + 1] * inv - m * m;
    float rstd = rsqrtf(var + 1e-5f);
    float w    = gnw[c] * rstd;
    float bias = gnb[c] - m * w;
    const __half2* src = (const __half2*)(g_op + e);
    float2 p0 = __half22float2(src[0]);
    float2 p1 = __half22float2(src[1]);
    float4 v = make_float4(p0.x * w + bias, p0.y * w + bias,
                           p1.x * w + bias, p1.y * w + bias);
    *(float4*)(out + e) = v;
}

// ---------------- launch ------------------------------------------------------
extern "C" void kernel_launch(void* const* d_in, const int* in_sizes, int n_in,
                              void* d_out, int out_size)
{
    const float* x    = (const float*)d_in[0];
    const float* wqkv = (const float*)d_in[1];
    const float* wout = (const float*)d_in[2];
    const float* bout = (const float*)d_in[3];
    const float* gnw  = (const float*)d_in[4];
    const float* gnb  = (const float*)d_in[5];
    float* out = (float*)d_out;

    cudaFuncSetAttribute(k_qkv, cudaFuncAttributeMaxDynamicSharedMemorySize, QKV_SMEM);

    k_zero<<<256, 256>>>();
    k_qkv<<<dim3(T_ / 128, B_), 256, QKV_SMEM>>>(x, wqkv);
    k_ctx<<<dim3(32, H_, B_), 256>>>();
    k_M<<<dim3(8, B_), 256>>>(wout);
    k_out<<<dim3(T_ / 128, B_), 256>>>(bout);
    k_norm<<<32768, 256>>>(gnw, gnb, out);
}

// round 11
// speedup vs baseline: 5.6812x; 1.1114x over previous
#include <cuda_runtime.h>
#include <cuda_fp16.h>
#include <cstdint>

#define B_ 16
#define C_ 128
#define T_ 16384
#define H_ 4
#define D_ 32
#define CT (C_ * T_)

__device__ __half g_eq[B_ * CT];
__device__ __half g_ek[B_ * CT];
__device__ __half g_v [B_ * CT];
__device__ __half g_op[B_ * CT];
__device__ float  g_Sq[B_ * C_];
__device__ float  g_Sk[B_ * C_];
__device__ float  g_ctx[B_ * H_ * D_ * D_];
__device__ float  g_M[B_ * C_ * C_];
__device__ float  g_stats[B_ * 2];

__device__ __forceinline__ float tf32r(float x) {
    uint32_t y;
    asm("cvt.rna.tf32.f32 %0, %1;" : "=r"(y) : "f"(x));
    return __uint_as_float(y);
}
__device__ __forceinline__ void mma_tf32(float* d, const uint32_t* a, const uint32_t* b2) {
    asm volatile("mma.sync.aligned.m16n8k8.row.col.f32.tf32.tf32.f32 "
        "{%0,%1,%2,%3}, {%4,%5,%6,%7}, {%8,%9}, {%0,%1,%2,%3};"
        : "+f"(d[0]), "+f"(d[1]), "+f"(d[2]), "+f"(d[3])
        : "r"(a[0]), "r"(a[1]), "r"(a[2]), "r"(a[3]), "r"(b2[0]), "r"(b2[1]));
}
__device__ __forceinline__ void mma_f16(float* d, const uint32_t* a, const uint32_t* b2) {
    asm volatile("mma.sync.aligned.m16n8k16.row.col.f32.f16.f16.f32 "
        "{%0,%1,%2,%3}, {%4,%5,%6,%7}, {%8,%9}, {%0,%1,%2,%3};"
        : "+f"(d[0]), "+f"(d[1]), "+f"(d[2]), "+f"(d[3])
        : "r"(a[0]), "r"(a[1]), "r"(a[2]), "r"(a[3]), "r"(b2[0]), "r"(b2[1]));
}

// ---------------- K0: zero ---------------------------------------------------
__global__ void k_zero() {
    int i = blockIdx.x * 256 + threadIdx.x;
    if (i < B_ * C_)           { g_Sq[i] = 0.f; g_Sk[i] = 0.f; }
    if (i < B_ * H_ * D_ * D_) g_ctx[i] = 0.f;
    if (i < B_ * 2)            g_stats[i] = 0.f;
}

// ---------------- K1: fused QKV GEMM via fp16 mma ----------------------------
// A = W [o][c] row-major halves (k-contiguous); B = x [c][t] halves: the two
// k-values of each B-fragment reg come from adjacent c-rows (2x LDS16 + pack;
// g-pairs share 32-bit words -> conflict-free).
__global__ __launch_bounds__(256, 2) void k_qkv(const float* __restrict__ x,
                                                const float* __restrict__ wqkv) {
    __shared__ __align__(16) __half Bs[128][136];   // x tile [c][t]
    __shared__ __align__(16) __half As[128][40];    // W chunk [o][32c]
    __shared__ float rsum[128];
    const int b = blockIdx.y, t0 = blockIdx.x * 128;
    const int tid = threadIdx.x, lane = tid & 31, wid = tid >> 5;
    const int wm = (wid >> 1) * 32, wn = (wid & 1) * 64;
    const int g = lane >> 2, c2 = (lane & 3) * 2;

    const float* xb = x + (size_t)b * CT;
#pragma unroll
    for (int it = 0; it < 16; it++) {
        int idx = tid + it * 256, row = idx >> 5, t4 = (idx & 31) * 4;
        float4 v = *(const float4*)(xb + (size_t)row * T_ + t0 + t4);
        *(__half2*)&Bs[row][t4]     = __floats2half2_rn(v.x, v.y);
        *(__half2*)&Bs[row][t4 + 2] = __floats2half2_rn(v.z, v.w);
    }

    for (int ot = 0; ot < 3; ot++) {
        float acc[2][8][4];
#pragma unroll
        for (int mi = 0; mi < 2; mi++)
#pragma unroll
            for (int ni = 0; ni < 8; ni++)
#pragma unroll
                for (int r = 0; r < 4; r++) acc[mi][ni][r] = 0.f;

        for (int kc = 0; kc < 4; kc++) {
            __syncthreads();
#pragma unroll
            for (int it = 0; it < 4; it++) {        // stage W chunk -> half
                int idx = tid + it * 256, row = idx >> 3, c4 = (idx & 7) * 4;
                float4 v = *(const float4*)(wqkv + (size_t)(ot * 128 + row) * 128
                                            + kc * 32 + c4);
                *(__half2*)&As[row][c4]     = __floats2half2_rn(v.x, v.y);
                *(__half2*)&As[row][c4 + 2] = __floats2half2_rn(v.z, v.w);
            }
            __syncthreads();
#pragma unroll
            for (int s = 0; s < 2; s++) {           // two k16 steps per kc
                const int ks = s * 16;
                const int kb = kc * 32 + ks;        // Bs row base (c index)
                uint32_t af[2][4], bf[8][2];
#pragma unroll
                for (int mi = 0; mi < 2; mi++) {
                    int r = wm + mi * 16 + g;
                    af[mi][0] = *(const uint32_t*)&As[r    ][ks +     c2];
                    af[mi][1] = *(const uint32_t*)&As[r + 8][ks +     c2];
                    af[mi][2] = *(const uint32_t*)&As[r    ][ks + 8 + c2];
                    af[mi][3] = *(const uint32_t*)&As[r + 8][ks + 8 + c2];
                }
#pragma unroll
                for (int ni = 0; ni < 8; ni++) {
                    int n = wn + ni * 8 + g;
                    __half2 p0 = __halves2half2(Bs[kb +     c2][n],
                                                Bs[kb +     c2 + 1][n]);
                    __half2 p1 = __halves2half2(Bs[kb + 8 + c2][n],
                                                Bs[kb + 8 + c2 + 1][n]);
                    bf[ni][0] = *(const uint32_t*)&p0;
                    bf[ni][1] = *(const uint32_t*)&p1;
                }
#pragma unroll
                for (int mi = 0; mi < 2; mi++)
#pragma unroll
                    for (int ni = 0; ni < 8; ni++)
                        mma_f16(acc[mi][ni], af[mi], bf[ni]);
            }
        }

        if (ot == 2) {                       // v: store half
            __half* dst = g_v + (size_t)b * CT;
#pragma unroll
            for (int mi = 0; mi < 2; mi++)
#pragma unroll
                for (int half = 0; half < 2; half++) {
                    int r = wm + mi * 16 + (lane >> 2) + half * 8;
#pragma unroll
                    for (int ni = 0; ni < 8; ni++)
                        *(__half2*)(dst + (size_t)r * T_ + t0 + wn + ni * 8
                                    + 2 * (lane & 3)) =
                            __floats2half2_rn(acc[mi][ni][half * 2],
                                              acc[mi][ni][half * 2 + 1]);
                }
        } else {                             // q/k: exp -> half, fp32 row sums
            __syncthreads();
            if (tid < 128) rsum[tid] = 0.f;
            __syncthreads();
            __half* dst = (ot == 0 ? g_eq : g_ek) + (size_t)b * CT;
#pragma unroll
            for (int mi = 0; mi < 2; mi++)
#pragma unroll
                for (int half = 0; half < 2; half++) {
                    int r = wm + mi * 16 + (lane >> 2) + half * 8;
                    float s = 0.f;
#pragma unroll
                    for (int ni = 0; ni < 8; ni++) {
                        float e0 = __expf(acc[mi][ni][half * 2]);
                        float e1 = __expf(acc[mi][ni][half * 2 + 1]);
                        s += e0 + e1;
                        *(__half2*)(dst + (size_t)r * T_ + t0 + wn + ni * 8
                                    + 2 * (lane & 3)) = __floats2half2_rn(e0, e1);
                    }
                    s += __shfl_xor_sync(0xffffffffu, s, 1);
                    s += __shfl_xor_sync(0xffffffffu, s, 2);
                    if ((lane & 3) == 0) atomicAdd(&rsum[r], s);
                }
            __syncthreads();
            float* S = (ot == 0 ? g_Sq : g_Sk) + b * C_;
            if (tid < 128) atomicAdd(&S[tid], rsum[tid]);
        }
    }
}

// ---------------- K2: ctx via fp16 tensor cores (R9-proven) ------------------
__global__ __launch_bounds__(256) void k_ctx() {
    const int b = blockIdx.z, h = blockIdx.y, sp = blockIdx.x;
    const __half* K = g_ek + (size_t)(b * C_ + h * D_) * T_;
    const __half* V = g_v  + (size_t)(b * C_ + h * D_) * T_;
    __shared__ __half ekh[32][136];
    __shared__ __half vh [32][136];
    __shared__ float cacc[D_ * D_];
    const int tid = threadIdx.x, lane = tid & 31, wid = tid >> 5;
    const int g = lane >> 2, c2 = (lane & 3) * 2;
    const int kb = wid * 16;

    for (int i = tid; i < D_ * D_; i += 256) cacc[i] = 0.f;

    float acc[2][4][4];
#pragma unroll
    for (int mi = 0; mi < 2; mi++)
#pragma unroll
        for (int ni = 0; ni < 4; ni++)
#pragma unroll
            for (int r = 0; r < 4; r++) acc[mi][ni][r] = 0.f;

    for (int n0 = sp * 512; n0 < sp * 512 + 512; n0 += 128) {
        for (int i = tid; i < 512; i += 256) {
            int row = i >> 4, c8 = (i & 15) * 8;
            *(uint4*)&ekh[row][c8] = *(const uint4*)(K + (size_t)row * T_ + n0 + c8);
            *(uint4*)&vh [row][c8] = *(const uint4*)(V + (size_t)row * T_ + n0 + c8);
        }
        __syncthreads();
        uint32_t af[2][4], bf[4][2];
#pragma unroll
        for (int mi = 0; mi < 2; mi++) {
            int r = mi * 16 + g;
            af[mi][0] = *(const uint32_t*)&ekh[r    ][kb +     c2];
            af[mi][1] = *(const uint32_t*)&ekh[r + 8][kb +     c2];
            af[mi][2] = *(const uint32_t*)&ekh[r    ][kb + 8 + c2];
            af[mi][3] = *(const uint32_t*)&ekh[r + 8][kb + 8 + c2];
        }
#pragma unroll
        for (int ni = 0; ni < 4; ni++) {
            int n = ni * 8 + g;
            bf[ni][0] = *(const uint32_t*)&vh[n][kb +     c2];
            bf[ni][1] = *(const uint32_t*)&vh[n][kb + 8 + c2];
        }
#pragma unroll
        for (int mi = 0; mi < 2; mi++)
#pragma unroll
            for (int ni = 0; ni < 4; ni++)
                mma_f16(acc[mi][ni], af[mi], bf[ni]);
        __syncthreads();
    }
#pragma unroll
    for (int mi = 0; mi < 2; mi++)
#pragma unroll
        for (int ni = 0; ni < 4; ni++)
#pragma unroll
            for (int r = 0; r < 4; r++) {
                int d = mi * 16 + g + (r >> 1) * 8;
                int e = ni * 8 + c2 + (r & 1);
                atomicAdd(&cacc[d * D_ + e], acc[mi][ni][r]);
            }
    __syncthreads();
    float* Cp = g_ctx + (size_t)(b * H_ + h) * (D_ * D_);
    for (int i = tid; i < D_ * D_; i += 256) atomicAdd(&Cp[i], cacc[i]);
}

// ---------------- K3: fused M = W_out x (scaled ctx) -------------------------
__global__ __launch_bounds__(256) void k_M(const float* __restrict__ w_out) {
    const int oseg = blockIdx.x, b = blockIdx.y;
    __shared__ float cf[H_ * D_ * 33];
    const int tid = threadIdx.x;
    const float scale = 0.17677669529663687f;  // 32^-0.5
    for (int i = tid; i < H_ * D_ * D_; i += 256) {
        int h = i >> 10, d = (i >> 5) & 31, e = i & 31;
        float sk = g_Sk[b * C_ + h * D_ + d], sq = g_Sq[b * C_ + h * D_ + d];
        cf[(h * D_ + d) * 33 + e] =
            scale * g_ctx[b * (H_ * D_ * D_) + i] / (sk * sq);
    }
    __syncthreads();
    for (int i = tid; i < 16 * C_; i += 256) {
        int o = oseg * 16 + (i >> 7), hd = i & 127;
        int h = hd >> 5, d = hd & 31;
        const float* wr = w_out + o * C_ + h * D_;
        const float* cr = cf + (h * D_ + d) * 33;
        float s = 0.f;
#pragma unroll
        for (int e = 0; e < 32; e++) s = fmaf(wr[e], cr[e], s);
        g_M[b * (C_ * C_) + o * C_ + hd] = s;
    }
}

// ---------------- K4: out = M @ eq + bias; GN moments; store fp16 ------------
__global__ __launch_bounds__(256, 2) void k_out(const float* __restrict__ b_out) {
    __shared__ __align__(16) float As[128][36];
    __shared__ __align__(16) float Bs[32][136];
    const int b = blockIdx.y, t0 = blockIdx.x * 128;
    const int tid = threadIdx.x, lane = tid & 31, wid = tid >> 5;
    const int wm = (wid >> 1) * 32, wn = (wid & 1) * 64;

    const float* Ag = g_M + b * 128 * 128;
    const __half* Bg = g_eq + (size_t)b * CT;

    float acc[2][8][4];
#pragma unroll
    for (int mi = 0; mi < 2; mi++)
#pragma unroll
        for (int ni = 0; ni < 8; ni++)
#pragma unroll
            for (int r = 0; r < 4; r++) acc[mi][ni][r] = 0.f;

    uint4 bpre[2];
#pragma unroll
    for (int it = 0; it < 2; it++) {
        int i = tid + it * 256, row = i >> 4, c8 = (i & 15) * 8;
        bpre[it] = *(const uint4*)(Bg + (size_t)row * T_ + t0 + c8);
    }
    for (int kc = 0; kc < 4; kc++) {
        __syncthreads();
#pragma unroll
        for (int it = 0; it < 4; it++) {
            int idx = tid + it * 256, row = idx >> 3, c4 = (idx & 7) * 4;
            float4 v = *(const float4*)(Ag + row * 128 + kc * 32 + c4);
            *(float4*)&As[row][c4] = make_float4(tf32r(v.x), tf32r(v.y),
                                                 tf32r(v.z), tf32r(v.w));
        }
#pragma unroll
        for (int it = 0; it < 2; it++) {
            int i = tid + it * 256, row = i >> 4, c8 = (i & 15) * 8;
            const __half2* hp = (const __half2*)&bpre[it];
#pragma unroll
            for (int q = 0; q < 4; q++) {
                float2 f = __half22float2(hp[q]);
                Bs[row][c8 + 2 * q]     = f.x;
                Bs[row][c8 + 2 * q + 1] = f.y;
            }
        }
        __syncthreads();
        if (kc < 3) {
#pragma unroll
            for (int it = 0; it < 2; it++) {
                int i = tid + it * 256, row = i >> 4, c8 = (i & 15) * 8;
                bpre[it] = *(const uint4*)(Bg + (size_t)((kc + 1) * 32 + row) * T_
                                           + t0 + c8);
            }
        }
#pragma unroll
        for (int k8 = 0; k8 < 4; k8++) {
            const int ks = k8 * 8;
            uint32_t af[2][4], bf[8][2];
#pragma unroll
            for (int mi = 0; mi < 2; mi++) {
                int r = wm + mi * 16 + (lane >> 2);
                af[mi][0] = __float_as_uint(As[r    ][ks +     (lane & 3)]);
                af[mi][1] = __float_as_uint(As[r + 8][ks +     (lane & 3)]);
                af[mi][2] = __float_as_uint(As[r    ][ks + 4 + (lane & 3)]);
                af[mi][3] = __float_as_uint(As[r + 8][ks + 4 + (lane & 3)]);
            }
#pragma unroll
            for (int ni = 0; ni < 8; ni++) {
                int n = wn + ni * 8 + (lane >> 2);
                bf[ni][0] = __float_as_uint(Bs[ks +     (lane & 3)][n]);
                bf[ni][1] = __float_as_uint(Bs[ks + 4 + (lane & 3)][n]);
            }
#pragma unroll
            for (int mi = 0; mi < 2; mi++)
#pragma unroll
                for (int ni = 0; ni < 8; ni++)
                    mma_tf32(acc[mi][ni], af[mi], bf[ni]);
        }
    }

    __half* dst = g_op + (size_t)b * CT;
    float s1 = 0.f, s2 = 0.f;
#pragma unroll
    for (int mi = 0; mi < 2; mi++)
#pragma unroll
        for (int half = 0; half < 2; half++) {
            int r = wm + mi * 16 + (lane >> 2) + half * 8;
            float bo = __ldg(&b_out[r]);
#pragma unroll
            for (int ni = 0; ni < 8; ni++) {
                float v0 = acc[mi][ni][half * 2]     + bo;
                float v1 = acc[mi][ni][half * 2 + 1] + bo;
                s1 += v0 + v1;
                s2 = fmaf(v0, v0, s2); s2 = fmaf(v1, v1, s2);
                *(__half2*)(dst + (size_t)r * T_ + t0 + wn + ni * 8
                            + 2 * (lane & 3)) = __floats2half2_rn(v0, v1);
            }
        }
#pragma unroll
    for (int o = 16; o > 0; o >>= 1) {
        s1 += __shfl_down_sync(0xffffffffu, s1, o);
        s2 += __shfl_down_sync(0xffffffffu, s2, o);
    }
    if (lane == 0) {
        atomicAdd(&g_stats[b * 2 + 0], s1);
        atomicAdd(&g_stats[b * 2 + 1], s2);
    }
}

// ---------------- K5: GroupNorm finalize (reads fp16 op) ---------------------
__global__ void k_norm(const float* __restrict__ gnw,
                       const float* __restrict__ gnb,
                       float* __restrict__ out) {
    int i4 = blockIdx.x * 256 + threadIdx.x;
    int e  = i4 * 4;
    int b  = e >> 21;
    int c  = (e >> 14) & 127;
    const float inv = 1.0f / (float)CT;
    float m    = g_stats[b * 2 + 0] * inv;
    float var  = g_stats[b * 2 + 1] * inv - m * m;
    float rstd = rsqrtf(var + 1e-5f);
    float w    = gnw[c] * rstd;
    float bias = gnb[c] - m * w;
    const __half2* src = (const __half2*)(g_op + e);
    float2 p0 = __half22float2(src[0]);
    float2 p1 = __half22float2(src[1]);
    float4 v = make_float4(p0.x * w + bias, p0.y * w + bias,
                           p1.x * w + bias, p1.y * w + bias);
    *(float4*)(out + e) = v;
}

// ---------------- launch ------------------------------------------------------
extern "C" void kernel_launch(void* const* d_in, const int* in_sizes, int n_in,
                              void* d_out, int out_size)
{
    const float* x    = (const float*)d_in[0];
    const float* wqkv = (const float*)d_in[1];
    const float* wout = (const float*)d_in[2];
    const float* bout = (const float*)d_in[3];
    const float* gnw  = (const float*)d_in[4];
    const float* gnb  = (const float*)d_in[5];
    float* out = (float*)d_out;

    k_zero<<<256, 256>>>();
    k_qkv<<<dim3(T_ / 128, B_), 256>>>(x, wqkv);
    k_ctx<<<dim3(32, H_, B_), 256>>>();
    k_M<<<dim3(8, B_), 256>>>(wout);
    k_out<<<dim3(T_ / 128, B_), 256>>>(bout);
    k_norm<<<32768, 256>>>(gnw, gnb, out);
}

// round 12
// speedup vs baseline: 5.9412x; 1.0458x over previous
#include <cuda_runtime.h>
#include <cuda_fp16.h>
#include <cstdint>

#define B_ 16
#define C_ 128
#define T_ 16384
#define H_ 4
#define D_ 32
#define CT (C_ * T_)

__device__ __half g_eq[B_ * CT];
__device__ __half g_ek[B_ * CT];
__device__ __half g_v [B_ * CT];
__device__ __half g_op[B_ * CT];
__device__ float  g_Sq[B_ * C_];
__device__ float  g_Sk[B_ * C_];
__device__ float  g_ctx[B_ * H_ * D_ * D_];
__device__ float  g_M[B_ * C_ * C_];
__device__ float  g_stats[B_ * 2];

#define MSCALE   1048576.0f        // 2^20: lift M out of fp16 subnormal range
#define IMSCALE  (1.0f / 1048576.0f)

__device__ __forceinline__ void mma_f16(float* d, const uint32_t* a, const uint32_t* b2) {
    asm volatile("mma.sync.aligned.m16n8k16.row.col.f32.f16.f16.f32 "
        "{%0,%1,%2,%3}, {%4,%5,%6,%7}, {%8,%9}, {%0,%1,%2,%3};"
        : "+f"(d[0]), "+f"(d[1]), "+f"(d[2]), "+f"(d[3])
        : "r"(a[0]), "r"(a[1]), "r"(a[2]), "r"(a[3]), "r"(b2[0]), "r"(b2[1]));
}

// ---------------- K0: zero ---------------------------------------------------
__global__ void k_zero() {
    int i = blockIdx.x * 256 + threadIdx.x;
    if (i < B_ * C_)           { g_Sq[i] = 0.f; g_Sk[i] = 0.f; }
    if (i < B_ * H_ * D_ * D_) g_ctx[i] = 0.f;
    if (i < B_ * 2)            g_stats[i] = 0.f;
}

// ---------------- K1: fused QKV GEMM via fp16 mma (R11-proven) ---------------
__global__ __launch_bounds__(256, 2) void k_qkv(const float* __restrict__ x,
                                                const float* __restrict__ wqkv) {
    __shared__ __align__(16) __half Bs[128][136];   // x tile [c][t]
    __shared__ __align__(16) __half As[128][40];    // W chunk [o][32c]
    __shared__ float rsum[128];
    const int b = blockIdx.y, t0 = blockIdx.x * 128;
    const int tid = threadIdx.x, lane = tid & 31, wid = tid >> 5;
    const int wm = (wid >> 1) * 32, wn = (wid & 1) * 64;
    const int g = lane >> 2, c2 = (lane & 3) * 2;

    const float* xb = x + (size_t)b * CT;
#pragma unroll
    for (int it = 0; it < 16; it++) {
        int idx = tid + it * 256, row = idx >> 5, t4 = (idx & 31) * 4;
        float4 v = *(const float4*)(xb + (size_t)row * T_ + t0 + t4);
        *(__half2*)&Bs[row][t4]     = __floats2half2_rn(v.x, v.y);
        *(__half2*)&Bs[row][t4 + 2] = __floats2half2_rn(v.z, v.w);
    }

    for (int ot = 0; ot < 3; ot++) {
        float acc[2][8][4];
#pragma unroll
        for (int mi = 0; mi < 2; mi++)
#pragma unroll
            for (int ni = 0; ni < 8; ni++)
#pragma unroll
                for (int r = 0; r < 4; r++) acc[mi][ni][r] = 0.f;

        for (int kc = 0; kc < 4; kc++) {
            __syncthreads();
#pragma unroll
            for (int it = 0; it < 4; it++) {
                int idx = tid + it * 256, row = idx >> 3, c4 = (idx & 7) * 4;
                float4 v = *(const float4*)(wqkv + (size_t)(ot * 128 + row) * 128
                                            + kc * 32 + c4);
                *(__half2*)&As[row][c4]     = __floats2half2_rn(v.x, v.y);
                *(__half2*)&As[row][c4 + 2] = __floats2half2_rn(v.z, v.w);
            }
            __syncthreads();
#pragma unroll
            for (int s = 0; s < 2; s++) {
                const int ks = s * 16;
                const int kb = kc * 32 + ks;
                uint32_t af[2][4], bf[8][2];
#pragma unroll
                for (int mi = 0; mi < 2; mi++) {
                    int r = wm + mi * 16 + g;
                    af[mi][0] = *(const uint32_t*)&As[r    ][ks +     c2];
                    af[mi][1] = *(const uint32_t*)&As[r + 8][ks +     c2];
                    af[mi][2] = *(const uint32_t*)&As[r    ][ks + 8 + c2];
                    af[mi][3] = *(const uint32_t*)&As[r + 8][ks + 8 + c2];
                }
#pragma unroll
                for (int ni = 0; ni < 8; ni++) {
                    int n = wn + ni * 8 + g;
                    __half2 p0 = __halves2half2(Bs[kb +     c2][n],
                                                Bs[kb +     c2 + 1][n]);
                    __half2 p1 = __halves2half2(Bs[kb + 8 + c2][n],
                                                Bs[kb + 8 + c2 + 1][n]);
                    bf[ni][0] = *(const uint32_t*)&p0;
                    bf[ni][1] = *(const uint32_t*)&p1;
                }
#pragma unroll
                for (int mi = 0; mi < 2; mi++)
#pragma unroll
                    for (int ni = 0; ni < 8; ni++)
                        mma_f16(acc[mi][ni], af[mi], bf[ni]);
            }
        }

        if (ot == 2) {
            __half* dst = g_v + (size_t)b * CT;
#pragma unroll
            for (int mi = 0; mi < 2; mi++)
#pragma unroll
                for (int half = 0; half < 2; half++) {
                    int r = wm + mi * 16 + (lane >> 2) + half * 8;
#pragma unroll
                    for (int ni = 0; ni < 8; ni++)
                        *(__half2*)(dst + (size_t)r * T_ + t0 + wn + ni * 8
                                    + 2 * (lane & 3)) =
                            __floats2half2_rn(acc[mi][ni][half * 2],
                                              acc[mi][ni][half * 2 + 1]);
                }
        } else {
            __syncthreads();
            if (tid < 128) rsum[tid] = 0.f;
            __syncthreads();
            __half* dst = (ot == 0 ? g_eq : g_ek) + (size_t)b * CT;
#pragma unroll
            for (int mi = 0; mi < 2; mi++)
#pragma unroll
                for (int half = 0; half < 2; half++) {
                    int r = wm + mi * 16 + (lane >> 2) + half * 8;
                    float s = 0.f;
#pragma unroll
                    for (int ni = 0; ni < 8; ni++) {
                        float e0 = __expf(acc[mi][ni][half * 2]);
                        float e1 = __expf(acc[mi][ni][half * 2 + 1]);
                        s += e0 + e1;
                        *(__half2*)(dst + (size_t)r * T_ + t0 + wn + ni * 8
                                    + 2 * (lane & 3)) = __floats2half2_rn(e0, e1);
                    }
                    s += __shfl_xor_sync(0xffffffffu, s, 1);
                    s += __shfl_xor_sync(0xffffffffu, s, 2);
                    if ((lane & 3) == 0) atomicAdd(&rsum[r], s);
                }
            __syncthreads();
            float* S = (ot == 0 ? g_Sq : g_Sk) + b * C_;
            if (tid < 128) atomicAdd(&S[tid], rsum[tid]);
        }
    }
}

// ---------------- K2: ctx via fp16 tensor cores (R9-proven) ------------------
__global__ __launch_bounds__(256) void k_ctx() {
    const int b = blockIdx.z, h = blockIdx.y, sp = blockIdx.x;
    const __half* K = g_ek + (size_t)(b * C_ + h * D_) * T_;
    const __half* V = g_v  + (size_t)(b * C_ + h * D_) * T_;
    __shared__ __half ekh[32][136];
    __shared__ __half vh [32][136];
    __shared__ float cacc[D_ * D_];
    const int tid = threadIdx.x, lane = tid & 31, wid = tid >> 5;
    const int g = lane >> 2, c2 = (lane & 3) * 2;
    const int kb = wid * 16;

    for (int i = tid; i < D_ * D_; i += 256) cacc[i] = 0.f;

    float acc[2][4][4];
#pragma unroll
    for (int mi = 0; mi < 2; mi++)
#pragma unroll
        for (int ni = 0; ni < 4; ni++)
#pragma unroll
            for (int r = 0; r < 4; r++) acc[mi][ni][r] = 0.f;

    for (int n0 = sp * 512; n0 < sp * 512 + 512; n0 += 128) {
        for (int i = tid; i < 512; i += 256) {
            int row = i >> 4, c8 = (i & 15) * 8;
            *(uint4*)&ekh[row][c8] = *(const uint4*)(K + (size_t)row * T_ + n0 + c8);
            *(uint4*)&vh [row][c8] = *(const uint4*)(V + (size_t)row * T_ + n0 + c8);
        }
        __syncthreads();
        uint32_t af[2][4], bf[4][2];
#pragma unroll
        for (int mi = 0; mi < 2; mi++) {
            int r = mi * 16 + g;
            af[mi][0] = *(const uint32_t*)&ekh[r    ][kb +     c2];
            af[mi][1] = *(const uint32_t*)&ekh[r + 8][kb +     c2];
            af[mi][2] = *(const uint32_t*)&ekh[r    ][kb + 8 + c2];
            af[mi][3] = *(const uint32_t*)&ekh[r + 8][kb + 8 + c2];
        }
#pragma unroll
        for (int ni = 0; ni < 4; ni++) {
            int n = ni * 8 + g;
            bf[ni][0] = *(const uint32_t*)&vh[n][kb +     c2];
            bf[ni][1] = *(const uint32_t*)&vh[n][kb + 8 + c2];
        }
#pragma unroll
        for (int mi = 0; mi < 2; mi++)
#pragma unroll
            for (int ni = 0; ni < 4; ni++)
                mma_f16(acc[mi][ni], af[mi], bf[ni]);
        __syncthreads();
    }
#pragma unroll
    for (int mi = 0; mi < 2; mi++)
#pragma unroll
        for (int ni = 0; ni < 4; ni++)
#pragma unroll
            for (int r = 0; r < 4; r++) {
                int d = mi * 16 + g + (r >> 1) * 8;
                int e = ni * 8 + c2 + (r & 1);
                atomicAdd(&cacc[d * D_ + e], acc[mi][ni][r]);
            }
    __syncthreads();
    float* Cp = g_ctx + (size_t)(b * H_ + h) * (D_ * D_);
    for (int i = tid; i < D_ * D_; i += 256) atomicAdd(&Cp[i], cacc[i]);
}

// ---------------- K3: fused M = W_out x (scaled ctx) -------------------------
// grid (32, B_): 4 o-rows per block (latency-bound; more blocks = faster)
__global__ __launch_bounds__(256) void k_M(const float* __restrict__ w_out) {
    const int oseg = blockIdx.x, b = blockIdx.y;
    __shared__ float cf[H_ * D_ * 33];
    const int tid = threadIdx.x;
    const float scale = 0.17677669529663687f;  // 32^-0.5
    for (int i = tid; i < H_ * D_ * D_; i += 256) {
        int h = i >> 10, d = (i >> 5) & 31, e = i & 31;
        float sk = g_Sk[b * C_ + h * D_ + d], sq = g_Sq[b * C_ + h * D_ + d];
        cf[(h * D_ + d) * 33 + e] =
            scale * g_ctx[b * (H_ * D_ * D_) + i] / (sk * sq);
    }
    __syncthreads();
    for (int i = tid; i < 4 * C_; i += 256) {
        int o = oseg * 4 + (i >> 7), hd = i & 127;
        int h = hd >> 5, d = hd & 31;
        const float* wr = w_out + o * C_ + h * D_;
        const float* cr = cf + (h * D_ + d) * 33;
        float s = 0.f;
#pragma unroll
        for (int e = 0; e < 32; e++) s = fmaf(wr[e], cr[e], s);
        g_M[b * (C_ * C_) + o * C_ + hd] = s;
    }
}

// ---------------- K4: out = M @ eq via fp16 mma; bias; GN moments ------------
// A = M*2^20 as half [o][c]; B = eq half [c][t] (raw copy); acc scaled back.
__global__ __launch_bounds__(256, 2) void k_out(const float* __restrict__ b_out) {
    __shared__ __align__(16) __half As[128][40];    // M chunk [o][32c]
    __shared__ __align__(16) __half Bs[32][136];    // eq chunk [32c][t]
    const int b = blockIdx.y, t0 = blockIdx.x * 128;
    const int tid = threadIdx.x, lane = tid & 31, wid = tid >> 5;
    const int wm = (wid >> 1) * 32, wn = (wid & 1) * 64;
    const int g = lane >> 2, c2 = (lane & 3) * 2;

    const float*  Ag = g_M + b * 128 * 128;
    const __half* Bg = g_eq + (size_t)b * CT;

    float acc[2][8][4];
#pragma unroll
    for (int mi = 0; mi < 2; mi++)
#pragma unroll
        for (int ni = 0; ni < 8; ni++)
#pragma unroll
            for (int r = 0; r < 4; r++) acc[mi][ni][r] = 0.f;

    uint4 bpre[2];
#pragma unroll
    for (int it = 0; it < 2; it++) {
        int i = tid + it * 256, row = i >> 4, c8 = (i & 15) * 8;
        bpre[it] = *(const uint4*)(Bg + (size_t)row * T_ + t0 + c8);
    }
    for (int kc = 0; kc < 4; kc++) {
        __syncthreads();
#pragma unroll
        for (int it = 0; it < 4; it++) {            // stage M chunk *2^20 -> half
            int idx = tid + it * 256, row = idx >> 3, c4 = (idx & 7) * 4;
            float4 v = *(const float4*)(Ag + row * 128 + kc * 32 + c4);
            *(__half2*)&As[row][c4]     = __floats2half2_rn(v.x * MSCALE, v.y * MSCALE);
            *(__half2*)&As[row][c4 + 2] = __floats2half2_rn(v.z * MSCALE, v.w * MSCALE);
        }
#pragma unroll
        for (int it = 0; it < 2; it++) {            // stage eq chunk (raw half)
            int i = tid + it * 256, row = i >> 4, c8 = (i & 15) * 8;
            *(uint4*)&Bs[row][c8] = bpre[it];
        }
        __syncthreads();
        if (kc < 3) {
#pragma unroll
            for (int it = 0; it < 2; it++) {
                int i = tid + it * 256, row = i >> 4, c8 = (i & 15) * 8;
                bpre[it] = *(const uint4*)(Bg + (size_t)((kc + 1) * 32 + row) * T_
                                           + t0 + c8);
            }
        }
#pragma unroll
        for (int s = 0; s < 2; s++) {
            const int ks = s * 16;
            uint32_t af[2][4], bf[8][2];
#pragma unroll
            for (int mi = 0; mi < 2; mi++) {
                int r = wm + mi * 16 + g;
                af[mi][0] = *(const uint32_t*)&As[r    ][ks +     c2];
                af[mi][1] = *(const uint32_t*)&As[r + 8][ks +     c2];
                af[mi][2] = *(const uint32_t*)&As[r    ][ks + 8 + c2];
                af[mi][3] = *(const uint32_t*)&As[r + 8][ks + 8 + c2];
            }
#pragma unroll
            for (int ni = 0; ni < 8; ni++) {
                int n = wn + ni * 8 + g;
                __half2 p0 = __halves2half2(Bs[ks +     c2][n],
                                            Bs[ks +     c2 + 1][n]);
                __half2 p1 = __halves2half2(Bs[ks + 8 + c2][n],
                                            Bs[ks + 8 + c2 + 1][n]);
                bf[ni][0] = *(const uint32_t*)&p0;
                bf[ni][1] = *(const uint32_t*)&p1;
            }
#pragma unroll
            for (int mi = 0; mi < 2; mi++)
#pragma unroll
                for (int ni = 0; ni < 8; ni++)
                    mma_f16(acc[mi][ni], af[mi], bf[ni]);
        }
    }

    __half* dst = g_op + (size_t)b * CT;
    float s1 = 0.f, s2 = 0.f;
#pragma unroll
    for (int mi = 0; mi < 2; mi++)
#pragma unroll
        for (int half = 0; half < 2; half++) {
            int r = wm + mi * 16 + (lane >> 2) + half * 8;
            float bo = __ldg(&b_out[r]);
#pragma unroll
            for (int ni = 0; ni < 8; ni++) {
                float v0 = acc[mi][ni][half * 2]     * IMSCALE + bo;
                float v1 = acc[mi][ni][half * 2 + 1] * IMSCALE + bo;
                s1 += v0 + v1;
                s2 = fmaf(v0, v0, s2); s2 = fmaf(v1, v1, s2);
                *(__half2*)(dst + (size_t)r * T_ + t0 + wn + ni * 8
                            + 2 * (lane & 3)) = __floats2half2_rn(v0, v1);
            }
        }
#pragma unroll
    for (int o = 16; o > 0; o >>= 1) {
        s1 += __shfl_down_sync(0xffffffffu, s1, o);
        s2 += __shfl_down_sync(0xffffffffu, s2, o);
    }
    if (lane == 0) {
        atomicAdd(&g_stats[b * 2 + 0], s1);
        atomicAdd(&g_stats[b * 2 + 1], s2);
    }
}

// ---------------- K5: GroupNorm finalize (reads fp16 op) ---------------------
__global__ void k_norm(const float* __restrict__ gnw,
                       const float* __restrict__ gnb,
                       float* __restrict__ out) {
    int i4 = blockIdx.x * 256 + threadIdx.x;
    int e  = i4 * 4;
    int b  = e >> 21;
    int c  = (e >> 14) & 127;
    const float inv = 1.0f / (float)CT;
    float m    = g_stats[b * 2 + 0] * inv;
    float var  = g_stats[b * 2 + 1] * inv - m * m;
    float rstd = rsqrtf(var + 1e-5f);
    float w    = gnw[c] * rstd;
    float bias = gnb[c] - m * w;
    const __half2* src = (const __half2*)(g_op + e);
    float2 p0 = __half22float2(src[0]);
    float2 p1 = __half22float2(src[1]);
    float4 v = make_float4(p0.x * w + bias, p0.y * w + bias,
                           p1.x * w + bias, p1.y * w + bias);
    *(float4*)(out + e) = v;
}

// ---------------- launch ------------------------------------------------------
extern "C" void kernel_launch(void* const* d_in, const int* in_sizes, int n_in,
                              void* d_out, int out_size)
{
    const float* x    = (const float*)d_in[0];
    const float* wqkv = (const float*)d_in[1];
    const float* wout = (const float*)d_in[2];
    const float* bout = (const float*)d_in[3];
    const float* gnw  = (const float*)d_in[4];
    const float* gnb  = (const float*)d_in[5];
    float* out = (float*)d_out;

    k_zero<<<256, 256>>>();
    k_qkv<<<dim3(T_ / 128, B_), 256>>>(x, wqkv);
    k_ctx<<<dim3(32, H_, B_), 256>>>();
    k_M<<<dim3(32, B_), 256>>>(wout);
    k_out<<<dim3(T_ / 128, B_), 256>>>(bout);
    k_norm<<<32768, 256>>>(gnw, gnb, out);
}

// round 14
// speedup vs baseline: 6.2954x; 1.0596x over previous
#include <cuda_runtime.h>
#include <cuda_fp16.h>
#include <cstdint>

#define B_ 16
#define C_ 128
#define T_ 16384
#define H_ 4
#define D_ 32
#define CT (C_ * T_)

__device__ __half g_eq[B_ * CT];
__device__ __half g_ek[B_ * CT];
__device__ __half g_v [B_ * CT];
__device__ __half g_op[B_ * CT];
__device__ float  g_Sq[B_ * C_];
__device__ float  g_Sk[B_ * C_];
__device__ float  g_ctx[B_ * H_ * D_ * D_];
__device__ float  g_M[B_ * C_ * C_];
__device__ float  g_stats[B_ * 2];

#define MSCALE   1048576.0f        // 2^20: lift M out of fp16 subnormal range
#define IMSCALE  (1.0f / 1048576.0f)

__device__ __forceinline__ void mma_f16(float* d, const uint32_t* a, const uint32_t* b2) {
    asm volatile("mma.sync.aligned.m16n8k16.row.col.f32.f16.f16.f32 "
        "{%0,%1,%2,%3}, {%4,%5,%6,%7}, {%8,%9}, {%0,%1,%2,%3};"
        : "+f"(d[0]), "+f"(d[1]), "+f"(d[2]), "+f"(d[3])
        : "r"(a[0]), "r"(a[1]), "r"(a[2]), "r"(a[3]), "r"(b2[0]), "r"(b2[1]));
}

// ---------------- K0: zero ---------------------------------------------------
__global__ void k_zero() {
    int i = blockIdx.x * 256 + threadIdx.x;
    if (i < B_ * C_)           { g_Sq[i] = 0.f; g_Sk[i] = 0.f; }
    if (i < B_ * H_ * D_ * D_) g_ctx[i] = 0.f;
    if (i < B_ * 2)            g_stats[i] = 0.f;
}

// ---------------- K1: fused QKV GEMM, c-pair-interleaved B tile --------------
// Bs2[cp][t] = half2( x[2cp][t], x[2cp+1][t] ) — B-fragment regs load as one
// LDS.32 (stride 136 words -> conflict-free: bank = 8*quad + g).
__global__ __launch_bounds__(256, 2) void k_qkv(const float* __restrict__ x,
                                                const float* __restrict__ wqkv) {
    __shared__ __align__(16) __half2 Bs2[64][136];  // x tile, c-pairs x t
    __shared__ __align__(16) __half  As[128][40];   // W chunk [o][32c]
    __shared__ float rsum[128];
    const int b = blockIdx.y, t0 = blockIdx.x * 128;
    const int tid = threadIdx.x, lane = tid & 31, wid = tid >> 5;
    const int wm = (wid >> 1) * 32, wn = (wid & 1) * 64;
    const int g = lane >> 2, c2 = (lane & 3) * 2;
    const int q = lane & 3;

    const float* xb = x + (size_t)b * CT;
#pragma unroll
    for (int it = 0; it < 8; it++) {                // stage + transpose-pack x
        int idx = tid + it * 256;                   // 0..2047
        int cp = idx >> 5, t4 = (idx & 31) * 4;
        float4 v0 = *(const float4*)(xb + (size_t)(2 * cp)     * T_ + t0 + t4);
        float4 v1 = *(const float4*)(xb + (size_t)(2 * cp + 1) * T_ + t0 + t4);
        __half2 w0 = __floats2half2_rn(v0.x, v1.x);
        __half2 w1 = __floats2half2_rn(v0.y, v1.y);
        __half2 w2 = __floats2half2_rn(v0.z, v1.z);
        __half2 w3 = __floats2half2_rn(v0.w, v1.w);
        uint4 u;
        u.x = *(uint32_t*)&w0; u.y = *(uint32_t*)&w1;
        u.z = *(uint32_t*)&w2; u.w = *(uint32_t*)&w3;
        *(uint4*)&Bs2[cp][t4] = u;
    }

    for (int ot = 0; ot < 3; ot++) {
        float acc[2][8][4];
#pragma unroll
        for (int mi = 0; mi < 2; mi++)
#pragma unroll
            for (int ni = 0; ni < 8; ni++)
#pragma unroll
                for (int r = 0; r < 4; r++) acc[mi][ni][r] = 0.f;

        for (int kc = 0; kc < 4; kc++) {
            __syncthreads();
#pragma unroll
            for (int it = 0; it < 4; it++) {        // stage W chunk -> half
                int idx = tid + it * 256, row = idx >> 3, c4 = (idx & 7) * 4;
                float4 v = *(const float4*)(wqkv + (size_t)(ot * 128 + row) * 128
                                            + kc * 32 + c4);
                *(__half2*)&As[row][c4]     = __floats2half2_rn(v.x, v.y);
                *(__half2*)&As[row][c4 + 2] = __floats2half2_rn(v.z, v.w);
            }
            __syncthreads();
#pragma unroll
            for (int s = 0; s < 2; s++) {
                const int ks = s * 16;
                const int rb = kc * 16 + s * 8 + q; // Bs2 row for this quad
                uint32_t af[2][4], bf[8][2];
#pragma unroll
                for (int mi = 0; mi < 2; mi++) {
                    int r = wm + mi * 16 + g;
                    af[mi][0] = *(const uint32_t*)&As[r    ][ks +     c2];
                    af[mi][1] = *(const uint32_t*)&As[r + 8][ks +     c2];
                    af[mi][2] = *(const uint32_t*)&As[r    ][ks + 8 + c2];
                    af[mi][3] = *(const uint32_t*)&As[r + 8][ks + 8 + c2];
                }
#pragma unroll
                for (int ni = 0; ni < 8; ni++) {
                    int n = wn + ni * 8 + g;
                    bf[ni][0] = *(const uint32_t*)&Bs2[rb    ][n];
                    bf[ni][1] = *(const uint32_t*)&Bs2[rb + 4][n];
                }
#pragma unroll
                for (int mi = 0; mi < 2; mi++)
#pragma unroll
                    for (int ni = 0; ni < 8; ni++)
                        mma_f16(acc[mi][ni], af[mi], bf[ni]);
            }
        }

        if (ot == 2) {
            __half* dst = g_v + (size_t)b * CT;
#pragma unroll
            for (int mi = 0; mi < 2; mi++)
#pragma unroll
                for (int half = 0; half < 2; half++) {
                    int r = wm + mi * 16 + (lane >> 2) + half * 8;
#pragma unroll
                    for (int ni = 0; ni < 8; ni++)
                        *(__half2*)(dst + (size_t)r * T_ + t0 + wn + ni * 8
                                    + 2 * (lane & 3)) =
                            __floats2half2_rn(acc[mi][ni][half * 2],
                                              acc[mi][ni][half * 2 + 1]);
                }
        } else {
            __syncthreads();
            if (tid < 128) rsum[tid] = 0.f;
            __syncthreads();
            __half* dst = (ot == 0 ? g_eq : g_ek) + (size_t)b * CT;
#pragma unroll
            for (int mi = 0; mi < 2; mi++)
#pragma unroll
                for (int half = 0; half < 2; half++) {
                    int r = wm + mi * 16 + (lane >> 2) + half * 8;
                    float s = 0.f;
#pragma unroll
                    for (int ni = 0; ni < 8; ni++) {
                        float e0 = __expf(acc[mi][ni][half * 2]);
                        float e1 = __expf(acc[mi][ni][half * 2 + 1]);
                        s += e0 + e1;
                        *(__half2*)(dst + (size_t)r * T_ + t0 + wn + ni * 8
                                    + 2 * (lane & 3)) = __floats2half2_rn(e0, e1);
                    }
                    s += __shfl_xor_sync(0xffffffffu, s, 1);
                    s += __shfl_xor_sync(0xffffffffu, s, 2);
                    if ((lane & 3) == 0) atomicAdd(&rsum[r], s);
                }
            __syncthreads();
            float* S = (ot == 0 ? g_Sq : g_Sk) + b * C_;
            if (tid < 128) atomicAdd(&S[tid], rsum[tid]);
        }
    }
}

// ---------------- K2: ctx via fp16 tensor cores (R9-proven) ------------------
__global__ __launch_bounds__(256) void k_ctx() {
    const int b = blockIdx.z, h = blockIdx.y, sp = blockIdx.x;
    const __half* K = g_ek + (size_t)(b * C_ + h * D_) * T_;
    const __half* V = g_v  + (size_t)(b * C_ + h * D_) * T_;
    __shared__ __half ekh[32][136];
    __shared__ __half vh [32][136];
    __shared__ float cacc[D_ * D_];
    const int tid = threadIdx.x, lane = tid & 31, wid = tid >> 5;
    const int g = lane >> 2, c2 = (lane & 3) * 2;
    const int kb = wid * 16;

    for (int i = tid; i < D_ * D_; i += 256) cacc[i] = 0.f;

    float acc[2][4][4];
#pragma unroll
    for (int mi = 0; mi < 2; mi++)
#pragma unroll
        for (int ni = 0; ni < 4; ni++)
#pragma unroll
            for (int r = 0; r < 4; r++) acc[mi][ni][r] = 0.f;

    for (int n0 = sp * 512; n0 < sp * 512 + 512; n0 += 128) {
        for (int i = tid; i < 512; i += 256) {
            int row = i >> 4, c8 = (i & 15) * 8;
            *(uint4*)&ekh[row][c8] = *(const uint4*)(K + (size_t)row * T_ + n0 + c8);
            *(uint4*)&vh [row][c8] = *(const uint4*)(V + (size_t)row * T_ + n0 + c8);
        }
        __syncthreads();
        uint32_t af[2][4], bf[4][2];
#pragma unroll
        for (int mi = 0; mi < 2; mi++) {
            int r = mi * 16 + g;
            af[mi][0] = *(const uint32_t*)&ekh[r    ][kb +     c2];
            af[mi][1] = *(const uint32_t*)&ekh[r + 8][kb +     c2];
            af[mi][2] = *(const uint32_t*)&ekh[r    ][kb + 8 + c2];
            af[mi][3] = *(const uint32_t*)&ekh[r + 8][kb + 8 + c2];
        }
#pragma unroll
        for (int ni = 0; ni < 4; ni++) {
            int n = ni * 8 + g;
            bf[ni][0] = *(const uint32_t*)&vh[n][kb +     c2];
            bf[ni][1] = *(const uint32_t*)&vh[n][kb + 8 + c2];
        }
#pragma unroll
        for (int mi = 0; mi < 2; mi++)
#pragma unroll
            for (int ni = 0; ni < 4; ni++)
                mma_f16(acc[mi][ni], af[mi], bf[ni]);
        __syncthreads();
    }
#pragma unroll
    for (int mi = 0; mi < 2; mi++)
#pragma unroll
        for (int ni = 0; ni < 4; ni++)
#pragma unroll
            for (int r = 0; r < 4; r++) {
                int d = mi * 16 + g + (r >> 1) * 8;
                int e = ni * 8 + c2 + (r & 1);
                atomicAdd(&cacc[d * D_ + e], acc[mi][ni][r]);
            }
    __syncthreads();
    float* Cp = g_ctx + (size_t)(b * H_ + h) * (D_ * D_);
    for (int i = tid; i < D_ * D_; i += 256) atomicAdd(&Cp[i], cacc[i]);
}

// ---------------- K3: fused M = W_out x (scaled ctx) -------------------------
__global__ __launch_bounds__(256) void k_M(const float* __restrict__ w_out) {
    const int oseg = blockIdx.x, b = blockIdx.y;
    __shared__ float cf[H_ * D_ * 33];
    const int tid = threadIdx.x;
    const float scale = 0.17677669529663687f;  // 32^-0.5
    for (int i = tid; i < H_ * D_ * D_; i += 256) {
        int h = i >> 10, d = (i >> 5) & 31, e = i & 31;
        float sk = g_Sk[b * C_ + h * D_ + d], sq = g_Sq[b * C_ + h * D_ + d];
        cf[(h * D_ + d) * 33 + e] =
            scale * g_ctx[b * (H_ * D_ * D_) + i] / (sk * sq);
    }
    __syncthreads();
    for (int i = tid; i < 4 * C_; i += 256) {
        int o = oseg * 4 + (i >> 7), hd = i & 127;
        int h = hd >> 5, d = hd & 31;
        const float* wr = w_out + o * C_ + h * D_;
        const float* cr = cf + (h * D_ + d) * 33;
        float s = 0.f;
#pragma unroll
        for (int e = 0; e < 32; e++) s = fmaf(wr[e], cr[e], s);
        g_M[b * (C_ * C_) + o * C_ + hd] = s;
    }
}

// ---------------- K4: out = M @ eq via fp16 mma; bias; GN moments ------------
// eq chunks repacked into c-pair half2 layout at staging (2 LDS.32 fragments).
__global__ __launch_bounds__(256, 2) void k_out(const float* __restrict__ b_out) {
    __shared__ __align__(16) __half  As[128][40];   // M chunk [o][32c]
    __shared__ __align__(16) __half2 Bs2[16][136];  // eq chunk, c-pairs x t
    const int b = blockIdx.y, t0 = blockIdx.x * 128;
    const int tid = threadIdx.x, lane = tid & 31, wid = tid >> 5;
    const int wm = (wid >> 1) * 32, wn = (wid & 1) * 64;
    const int g = lane >> 2, c2 = (lane & 3) * 2;
    const int q = lane & 3;

    const float*  Ag = g_M + b * 128 * 128;
    const __half* Bg = g_eq + (size_t)b * CT;

    float acc[2][8][4];
#pragma unroll
    for (int mi = 0; mi < 2; mi++)
#pragma unroll
        for (int ni = 0; ni < 8; ni++)
#pragma unroll
            for (int r = 0; r < 4; r++) acc[mi][ni][r] = 0.f;

    const int pcp = tid >> 4, pt8 = (tid & 15) * 8;     // prefetch coords
    uint4 bp0 = *(const uint4*)(Bg + (size_t)(2 * pcp)     * T_ + t0 + pt8);
    uint4 bp1 = *(const uint4*)(Bg + (size_t)(2 * pcp + 1) * T_ + t0 + pt8);

    for (int kc = 0; kc < 4; kc++) {
        __syncthreads();
#pragma unroll
        for (int it = 0; it < 4; it++) {            // stage M chunk *2^20 -> half
            int idx = tid + it * 256, row = idx >> 3, c4 = (idx & 7) * 4;
            float4 v = *(const float4*)(Ag + row * 128 + kc * 32 + c4);
            *(__half2*)&As[row][c4]     = __floats2half2_rn(v.x * MSCALE, v.y * MSCALE);
            *(__half2*)&As[row][c4 + 2] = __floats2half2_rn(v.z * MSCALE, v.w * MSCALE);
        }
        {                                           // interleave eq chunk
            const __half* h0 = (const __half*)&bp0;
            const __half* h1 = (const __half*)&bp1;
            uint4 u0, u1;
            __half2 w;
            w = __halves2half2(h0[0], h1[0]); u0.x = *(uint32_t*)&w;
            w = __halves2half2(h0[1], h1[1]); u0.y = *(uint32_t*)&w;
            w = __halves2half2(h0[2], h1[2]); u0.z = *(uint32_t*)&w;
            w = __halves2half2(h0[3], h1[3]); u0.w = *(uint32_t*)&w;
            w = __halves2half2(h0[4], h1[4]); u1.x = *(uint32_t*)&w;
            w = __halves2half2(h0[5], h1[5]); u1.y = *(uint32_t*)&w;
            w = __halves2half2(h0[6], h1[6]); u1.z = *(uint32_t*)&w;
            w = __halves2half2(h0[7], h1[7]); u1.w = *(uint32_t*)&w;
            *(uint4*)&Bs2[pcp][pt8]     = u0;
            *(uint4*)&Bs2[pcp][pt8 + 4] = u1;
        }
        __syncthreads();
        if (kc < 3) {
            bp0 = *(const uint4*)(Bg + (size_t)((kc + 1) * 32 + 2 * pcp)     * T_
                                  + t0 + pt8);
            bp1 = *(const uint4*)(Bg + (size_t)((kc + 1) * 32 + 2 * pcp + 1) * T_
                                  + t0 + pt8);
        }
#pragma unroll
        for (int s = 0; s < 2; s++) {
            const int ks = s * 16;
            const int rb = s * 8 + q;
            uint32_t af[2][4], bf[8][2];
#pragma unroll
            for (int mi = 0; mi < 2; mi++) {
                int r = wm + mi * 16 + g;
                af[mi][0] = *(const uint32_t*)&As[r    ][ks +     c2];
                af[mi][1] = *(const uint32_t*)&As[r + 8][ks +     c2];
                af[mi][2] = *(const uint32_t*)&As[r    ][ks + 8 + c2];
                af[mi][3] = *(const uint32_t*)&As[r + 8][ks + 8 + c2];
            }
#pragma unroll
            for (int ni = 0; ni < 8; ni++) {
                int n = wn + ni * 8 + g;
                bf[ni][0] = *(const uint32_t*)&Bs2[rb    ][n];
                bf[ni][1] = *(const uint32_t*)&Bs2[rb + 4][n];
            }
#pragma unroll
            for (int mi = 0; mi < 2; mi++)
#pragma unroll
                for (int ni = 0; ni < 8; ni++)
                    mma_f16(acc[mi][ni], af[mi], bf[ni]);
        }
    }

    __half* dst = g_op + (size_t)b * CT;
    float s1 = 0.f, s2 = 0.f;
#pragma unroll
    for (int mi = 0; mi < 2; mi++)
#pragma unroll
        for (int half = 0; half < 2; half++) {
            int r = wm + mi * 16 + (lane >> 2) + half * 8;
            float bo = __ldg(&b_out[r]);
#pragma unroll
            for (int ni = 0; ni < 8; ni++) {
                float v0 = acc[mi][ni][half * 2]     * IMSCALE + bo;
                float v1 = acc[mi][ni][half * 2 + 1] * IMSCALE + bo;
                s1 += v0 + v1;
                s2 = fmaf(v0, v0, s2); s2 = fmaf(v1, v1, s2);
                *(__half2*)(dst + (size_t)r * T_ + t0 + wn + ni * 8
                            + 2 * (lane & 3)) = __floats2half2_rn(v0, v1);
            }
        }
#pragma unroll
    for (int o = 16; o > 0; o >>= 1) {
        s1 += __shfl_down_sync(0xffffffffu, s1, o);
        s2 += __shfl_down_sync(0xffffffffu, s2, o);
    }
    if (lane == 0) {
        atomicAdd(&g_stats[b * 2 + 0], s1);
        atomicAdd(&g_stats[b * 2 + 1], s2);
    }
}

// ---------------- K5: GroupNorm finalize (reads fp16 op) ---------------------
__global__ void k_norm(const float* __restrict__ gnw,
                       const float* __restrict__ gnb,
                       float* __restrict__ out) {
    int i4 = blockIdx.x * 256 + threadIdx.x;
    int e  = i4 * 4;
    int b  = e >> 21;
    int c  = (e >> 14) & 127;
    const float inv = 1.0f / (float)CT;
    float m    = g_stats[b * 2 + 0] * inv;
    float var  = g_stats[b * 2 + 1] * inv - m * m;
    float rstd = rsqrtf(var + 1e-5f);
    float w    = gnw[c] * rstd;
    float bias = gnb[c] - m * w;
    const __half2* src = (const __half2*)(g_op + e);
    float2 p0 = __half22float2(src[0]);
    float2 p1 = __half22float2(src[1]);
    float4 v = make_float4(p0.x * w + bias, p0.y * w + bias,
                           p1.x * w + bias, p1.y * w + bias);
    *(float4*)(out + e) = v;
}

// ---------------- launch ------------------------------------------------------
extern "C" void kernel_launch(void* const* d_in, const int* in_sizes, int n_in,
                              void* d_out, int out_size)
{
    const float* x    = (const float*)d_in[0];
    const float* wqkv = (const float*)d_in[1];
    const float* wout = (const float*)d_in[2];
    const float* bout = (const float*)d_in[3];
    const float* gnw  = (const float*)d_in[4];
    const float* gnb  = (const float*)d_in[5];
    float* out = (float*)d_out;

    k_zero<<<256, 256>>>();
    k_qkv<<<dim3(T_ / 128, B_), 256>>>(x, wqkv);
    k_ctx<<<dim3(32, H_, B_), 256>>>();
    k_M<<<dim3(32, B_), 256>>>(wout);
    k_out<<<dim3(T_ / 128, B_), 256>>>(bout);
    k_norm<<<32768, 256>>>(gnw, gnb, out);
}